// round 5
// baseline (speedup 1.0000x reference)
#include <cuda_runtime.h>
#include <cuda_bf16.h>
#include <math.h>
#include <stdint.h>

#define N_  10000
#define E_  20000
#define B_  400
#define ND_ 32
#define ED_ 16
#define D_  64
#define DD_ 4096   // D*D

// ---------------- scratch (device globals; no cudaMalloc allowed) ----------------
__device__ float g_h[N_ * D_];            // node hidden / out
__device__ __nv_bfloat16 g_rhi[E_ * D_];  // edge MLP hidden, bf16 hi
__device__ __nv_bfloat16 g_rlo[E_ * D_];  // bf16 lo (residual)
__device__ __nv_bfloat16 g_w2hi[DD_ * D_]; // W_e2 split hi [4096][64]
__device__ __nv_bfloat16 g_w2lo[DD_ * D_];
__device__ float g_agg[3 * N_ * D_];      // scatter accumulators (one per iteration)
__device__ float g_cnt[N_];               // dst degree
__device__ int   g_src[E_], g_dst[E_], g_batch[N_];
__device__ int   g_flags[2];              // [0]=edge_index is int64, [1]=batch is int64
__device__ int   g_gcnt[B_];
__device__ int   g_ptr[B_ + 1];
__device__ float g_qstar[B_ * 2 * D_];
__device__ float g_hl[B_ * D_];
__device__ float g_cl[B_ * D_];
__device__ float g_e[N_];                 // per-node attention logits / weights

__device__ __forceinline__ float sigm(float x) { return 1.f / (1.f + expf(-x)); }

__device__ __forceinline__ uint32_t smem_u32(const void* p) {
    uint32_t a;
    asm("{ .reg .u64 t; cvta.to.shared.u64 t, %1; cvt.u32.u64 %0, t; }" : "=r"(a) : "l"(p));
    return a;
}
__device__ __forceinline__ void cp16(uint32_t dst, const void* src) {
    asm volatile("cp.async.cg.shared.global [%0], [%1], 16;" :: "r"(dst), "l"(src));
}

// ---------------- dtype detection (int64 vs int32 delivered buffers) ----------------
__global__ void detect_kernel(const void* ei, const void* ba) {
    if (threadIdx.x != 0) return;
    {
        const long long* p = (const long long*)ei;
        int ok = 1;
        for (int i = 0; i < 8; i++) { long long v = p[i]; if (v < 0 || v >= N_) ok = 0; }
        for (int i = 0; i < 8; i++) { long long v = p[2 * E_ / 2 - 8 + i]; if (v < 0 || v >= N_) ok = 0; }
        g_flags[0] = ok;
    }
    {
        const long long* p = (const long long*)ba;
        int ok = 1;
        for (int i = 0; i < 8; i++) { long long v = p[i]; if (v < 0 || v >= B_) ok = 0; }
        for (int i = 0; i < 8; i++) { long long v = p[N_ / 2 - 8 + i]; if (v < 0 || v >= B_) ok = 0; }
        g_flags[1] = ok;
    }
}

__global__ void convert_kernel(const void* ei, const void* ba) {
    int i = blockIdx.x * blockDim.x + threadIdx.x;
    if (i < E_) {
        if (g_flags[0]) {
            const long long* p = (const long long*)ei;
            g_src[i] = (int)p[i];
            g_dst[i] = (int)p[E_ + i];
        } else {
            const int* p = (const int*)ei;
            g_src[i] = p[i];
            g_dst[i] = p[E_ + i];
        }
    }
    if (i < N_) {
        if (g_flags[1]) {
            const long long* p = (const long long*)ba;
            g_batch[i] = (int)p[i];
        } else {
            const int* p = (const int*)ba;
            g_batch[i] = p[i];
        }
    }
}

// ---------------- fused zero init ----------------
__global__ void init_zero_kernel() {
    int i = blockIdx.x * blockDim.x + threadIdx.x;
    int stride = gridDim.x * blockDim.x;
    for (int j = i; j < 3 * N_ * D_; j += stride) g_agg[j] = 0.f;
    if (i < N_) g_cnt[i] = 0.f;
    if (i < B_) g_gcnt[i] = 0;
    if (i < B_ * 2 * D_) g_qstar[i] = 0.f;
    if (i < B_ * D_) { g_hl[i] = 0.f; g_cl[i] = 0.f; }
}

__global__ void counts_kernel() {
    int i = blockIdx.x * blockDim.x + threadIdx.x;
    if (i < E_) atomicAdd(&g_cnt[g_dst[i]], 1.0f);
    if (i < N_) atomicAdd(&g_gcnt[g_batch[i]], 1);
}

__global__ void scan_ptr_kernel() {
    if (threadIdx.x != 0) return;
    int acc = 0;
    g_ptr[0] = 0;
    for (int b = 0; b < B_; b++) { acc += g_gcnt[b]; g_ptr[b + 1] = acc; }
}

// ---------------- W_e2 split to bf16 hi/lo ----------------
__global__ void w2split_kernel(const float* __restrict__ W) {
    int i = blockIdx.x * blockDim.x + threadIdx.x;
    if (i >= DD_ * D_) return;
    float w = W[i];
    __nv_bfloat16 hi = __float2bfloat16(w);
    __nv_bfloat16 lo = __float2bfloat16(w - __bfloat162float(hi));
    g_w2hi[i] = hi;
    g_w2lo[i] = lo;
}

// ---------------- fused encoders: in_linear + edge_hidden(+split) ----------------
__global__ void encoders_kernel(const float* __restrict__ x,
                                const float* __restrict__ W_in, const float* __restrict__ b_in,
                                const float* __restrict__ ea,
                                const float* __restrict__ W_e1, const float* __restrict__ b_e1) {
    int i = blockIdx.x * blockDim.x + threadIdx.x;
    if (i < N_ * D_) {
        int n = i >> 6, f = i & 63;
        float acc = b_in[f];
        const float* xr = x + n * ND_;
        const float* wr = W_in + f * ND_;
#pragma unroll
        for (int k = 0; k < ND_; k++) acc += xr[k] * wr[k];
        g_h[i] = fmaxf(acc, 0.f);
    } else if (i < N_ * D_ + E_ * D_) {
        int j = i - N_ * D_;
        int e = j >> 6, f = j & 63;
        float acc = b_e1[f];
        const float* er = ea + e * ED_;
        const float* wr = W_e1 + f * ED_;
#pragma unroll
        for (int k = 0; k < ED_; k++) acc += er[k] * wr[k];
        float r = fmaxf(acc, 0.f);
        __nv_bfloat16 hi = __float2bfloat16(r);
        __nv_bfloat16 lo = __float2bfloat16(r - __bfloat162float(hi));
        g_rhi[j] = hi;
        g_rlo[j] = lo;
    }
}

// ============ fused NNConv message GEMM (no ew materialization) ============
// Per CTA: 64 edges, 128 threads (4 warps, warp = 16 rows x 64 cols).
// msg[e,f] = sum_d h[src_e,d] * (R[e,:]@W2_d^T)[f]  + (h[src_e,:]@B2)[f]
// Q_d computed on tensor cores (bf16 hi/lo 3-product split, fp32 acc),
// scaled by fp32 h[:,d], accumulated in registers; atomic scatter at end.
#define EWPAD 72     // bf16 row stride (144B): conflict-free ldmatrix phases
#define MS_RHI 0
#define MS_RLO 9216
#define MS_W2  18432                 // 2 bufs x (hi 9216 + lo 9216)
#define MS_HD  55296                 // 64 x 65 fp32 (transposed h, padded)
#define MS_B2  71936                 // 4096 fp32
#define MS_TOT 88320

__device__ __forceinline__ void ldsm4(uint32_t addr, uint32_t* r) {
    asm volatile("ldmatrix.sync.aligned.m8n8.x4.shared.b16 {%0,%1,%2,%3}, [%4];"
                 : "=r"(r[0]), "=r"(r[1]), "=r"(r[2]), "=r"(r[3]) : "r"(addr));
}
__device__ __forceinline__ void mma_bf16(float* c, const uint32_t* a, uint32_t b0, uint32_t b1) {
    asm volatile(
        "mma.sync.aligned.m16n8k16.row.col.f32.bf16.bf16.f32 "
        "{%0,%1,%2,%3}, {%4,%5,%6,%7}, {%8,%9}, {%0,%1,%2,%3};"
        : "+f"(c[0]), "+f"(c[1]), "+f"(c[2]), "+f"(c[3])
        : "r"(a[0]), "r"(a[1]), "r"(a[2]), "r"(a[3]), "r"(b0), "r"(b1));
}

__device__ __forceinline__ void stage_w2(char* smem, uint32_t sb, int buf, int d, int tid) {
    uint32_t bufh = sb + MS_W2 + buf * 18432;
    for (int i = tid; i < 512; i += 128) {
        int row = i >> 3, k8 = i & 7;
        uint32_t off = (uint32_t)(row * EWPAD + k8 * 8) * 2;
        size_t gi = (size_t)(d * 64 + row) * 64 + k8 * 8;
        cp16(bufh + off, &g_w2hi[gi]);
        cp16(bufh + 9216 + off, &g_w2lo[gi]);
    }
    asm volatile("cp.async.commit_group;" ::: "memory");
}

__global__ void __launch_bounds__(128) msg_mma_kernel(const float* __restrict__ b2, int it) {
    extern __shared__ char smem[];
    uint32_t sb = smem_u32(smem);
    int tid = threadIdx.x;
    int e0 = blockIdx.x * 64;
    int w = tid >> 5, lane = tid & 31;
    int r8 = lane & 7, q = lane >> 3;
    int g = lane >> 2, qq = lane & 3;

    // stage R hi/lo (padded)
    for (int i = tid; i < 512; i += 128) {
        int row = i >> 3, k8 = i & 7;
        int e = e0 + row;
        uint32_t off = (uint32_t)(row * EWPAD + k8 * 8) * 2;
        uint4 vh = make_uint4(0, 0, 0, 0), vl = make_uint4(0, 0, 0, 0);
        if (e < E_) {
            vh = *(const uint4*)&g_rhi[e * 64 + k8 * 8];
            vl = *(const uint4*)&g_rlo[e * 64 + k8 * 8];
        }
        *(uint4*)(smem + MS_RHI + off) = vh;
        *(uint4*)(smem + MS_RLO + off) = vl;
    }
    // stage HD (transposed h gather) + B2
    for (int i = tid; i < 4096; i += 128) {
        int e = i >> 6, d = i & 63;
        int ee = e0 + e;
        float v = (ee < E_) ? g_h[g_src[ee] * 64 + d] : 0.f;
        *(float*)(smem + MS_HD + (d * 65 + e) * 4) = v;
        *(float*)(smem + MS_B2 + i * 4) = b2[i];
    }
    // prefetch W2 chunk d=0
    stage_w2(smem, sb, 0, 0, tid);
    __syncthreads();

    // A fragments from R (persist for whole d-loop)
    int a_row = ((q & 1) ? 8 : 0) + r8;
    int a_col = (q >= 2) ? 8 : 0;
    int b_row = ((q >= 2) ? 8 : 0) + r8;
    int b_col = (q & 1) ? 8 : 0;

    uint32_t arhi[4][4], arlo[4][4];
#pragma unroll
    for (int k0 = 0; k0 < 4; k0++) {
        uint32_t ad = sb + MS_RHI + (uint32_t)((w * 16 + a_row) * EWPAD + k0 * 16 + a_col) * 2;
        ldsm4(ad, arhi[k0]);
        ldsm4(ad + 9216, arlo[k0]);
    }

    int el0 = w * 16 + g;   // local row of c[.][0,1]; +8 for c[.][2,3]
    float msg[8][4];
#pragma unroll
    for (int n = 0; n < 8; n++)
#pragma unroll
        for (int j = 0; j < 4; j++) msg[n][j] = 0.f;

    // bias term: msg += h @ B2  (fp32)
#pragma unroll 2
    for (int d = 0; d < 64; d++) {
        float hv0 = *(const float*)(smem + MS_HD + (d * 65 + el0) * 4);
        float hv1 = *(const float*)(smem + MS_HD + (d * 65 + el0 + 8) * 4);
#pragma unroll
        for (int n = 0; n < 8; n++) {
            float2 bb = *(const float2*)(smem + MS_B2 + (d * 64 + n * 8 + qq * 2) * 4);
            msg[n][0] += hv0 * bb.x;
            msg[n][1] += hv0 * bb.y;
            msg[n][2] += hv1 * bb.x;
            msg[n][3] += hv1 * bb.y;
        }
    }

    // main d-loop: Q_d = R @ W2_d^T on tensor cores; msg += h[:,d] * Q_d
    for (int d = 0; d < 64; d++) {
        if (d + 1 < 64) stage_w2(smem, sb, (d + 1) & 1, d + 1, tid);
        if (d + 1 < 64) asm volatile("cp.async.wait_group 1;" ::: "memory");
        else            asm volatile("cp.async.wait_group 0;" ::: "memory");
        __syncthreads();

        uint32_t bufh = sb + MS_W2 + (uint32_t)((d & 1) * 18432);
        float qd[8][4];
#pragma unroll
        for (int n = 0; n < 8; n++)
#pragma unroll
            for (int j = 0; j < 4; j++) qd[n][j] = 0.f;

#pragma unroll
        for (int k0 = 0; k0 < 4; k0++) {
#pragma unroll
            for (int p = 0; p < 4; p++) {
                uint32_t bd = bufh + (uint32_t)((p * 16 + b_row) * EWPAD + k0 * 16 + b_col) * 2;
                uint32_t bhi[4], blo[4];
                ldsm4(bd, bhi);
                ldsm4(bd + 9216, blo);
#pragma unroll
                for (int nn = 0; nn < 2; nn++) {
                    int n = p * 2 + nn, s = nn * 2;
                    mma_bf16(qd[n], arhi[k0], bhi[s], bhi[s + 1]);
                    mma_bf16(qd[n], arhi[k0], blo[s], blo[s + 1]);
                    mma_bf16(qd[n], arlo[k0], bhi[s], bhi[s + 1]);
                }
            }
        }
        float hv0 = *(const float*)(smem + MS_HD + (d * 65 + el0) * 4);
        float hv1 = *(const float*)(smem + MS_HD + (d * 65 + el0 + 8) * 4);
#pragma unroll
        for (int n = 0; n < 8; n++) {
            msg[n][0] += hv0 * qd[n][0];
            msg[n][1] += hv0 * qd[n][1];
            msg[n][2] += hv1 * qd[n][2];
            msg[n][3] += hv1 * qd[n][3];
        }
        __syncthreads();
    }

    // scatter to agg[dst]
    float* agg = &g_agg[(size_t)it * N_ * D_];
    int ge0 = e0 + el0, ge1 = e0 + el0 + 8;
    int dst0 = (ge0 < E_) ? g_dst[ge0] : -1;
    int dst1 = (ge1 < E_) ? g_dst[ge1] : -1;
#pragma unroll
    for (int n = 0; n < 8; n++) {
        int col = n * 8 + qq * 2;
        if (dst0 >= 0) {
            atomicAdd(&agg[dst0 * 64 + col], msg[n][0]);
            atomicAdd(&agg[dst0 * 64 + col + 1], msg[n][1]);
        }
        if (dst1 >= 0) {
            atomicAdd(&agg[dst1 * 64 + col], msg[n][2]);
            atomicAdd(&agg[dst1 * 64 + col + 1], msg[n][3]);
        }
    }
}

// ---------------- GRU update over node tiles of 16 ----------------
__global__ void __launch_bounds__(192) gru_kernel(const float* __restrict__ Wih,
                                                  const float* __restrict__ bih,
                                                  const float* __restrict__ Whh,
                                                  const float* __restrict__ bhh,
                                                  const float* __restrict__ bconv,
                                                  int it) {
    __shared__ float Msm[16][64];
    __shared__ float Hsm[16][64];
    __shared__ float GI[16][192];
    __shared__ float GH[16][192];
    int n0 = blockIdx.x * 16;
    int tid = threadIdx.x;
    const float* agg = &g_agg[(size_t)it * N_ * D_];

    for (int idx = tid; idx < 16 * 64; idx += 192) {
        int m = idx >> 6, k = idx & 63;
        int n = n0 + m;
        if (n < N_) {
            float cdeg = fmaxf(g_cnt[n], 1.0f);
            Msm[m][k] = fmaxf(agg[n * 64 + k] / cdeg + bconv[k], 0.f);
            Hsm[m][k] = g_h[n * 64 + k];
        } else {
            Msm[m][k] = 0.f;
            Hsm[m][k] = 0.f;
        }
    }
    __syncthreads();

    float wih[64], whh[64];
    const float* wi = Wih + tid * 64;
    const float* wh = Whh + tid * 64;
#pragma unroll
    for (int k = 0; k < 64; k++) { wih[k] = __ldg(&wi[k]); whh[k] = __ldg(&wh[k]); }
    float bi = bih[tid], bh = bhh[tid];

#pragma unroll 4
    for (int m = 0; m < 16; m++) {
        float ai = bi, ah = bh;
#pragma unroll
        for (int k = 0; k < 64; k++) {
            ai += Msm[m][k] * wih[k];
            ah += Hsm[m][k] * whh[k];
        }
        GI[m][tid] = ai;
        GH[m][tid] = ah;
    }
    __syncthreads();

    for (int idx = tid; idx < 16 * 64; idx += 192) {
        int m = idx >> 6, f = idx & 63;
        int n = n0 + m;
        if (n >= N_) continue;
        float r = sigm(GI[m][f] + GH[m][f]);
        float z = sigm(GI[m][64 + f] + GH[m][64 + f]);
        float nn = tanhf(GI[m][128 + f] + r * GH[m][128 + f]);
        float hnew = (1.f - z) * nn + z * Hsm[m][f];
        g_h[n * 64 + f] = hnew;
    }
}

// ---------------- Set2Set LSTM cell (8 graphs per 256-thread block) ----------------
__global__ void lstm_kernel(const float* __restrict__ Wih, const float* __restrict__ bih,
                            const float* __restrict__ Whh, const float* __restrict__ bhh) {
    __shared__ float qs[8][128];
    __shared__ float hs[8][64];
    __shared__ float gsm[8][256];
    int b0 = blockIdx.x * 8;
    int tid = threadIdx.x;

    for (int idx = tid; idx < 8 * 128; idx += 256) {
        int g = idx >> 7, k = idx & 127;
        int b = b0 + g;
        qs[g][k] = (b < B_) ? g_qstar[b * 128 + k] : 0.f;
    }
    for (int idx = tid; idx < 8 * 64; idx += 256) {
        int g = idx >> 6, k = idx & 63;
        int b = b0 + g;
        hs[g][k] = (b < B_) ? g_hl[b * 64 + k] : 0.f;
    }
    __syncthreads();

    int j = tid;
    float acc[8];
    float bsum = bih[j] + bhh[j];
#pragma unroll
    for (int g = 0; g < 8; g++) acc[g] = bsum;
    const float* wi = Wih + j * 128;
    const float* wh = Whh + j * 64;
#pragma unroll 4
    for (int k = 0; k < 128; k++) {
        float w = __ldg(&wi[k]);
#pragma unroll
        for (int g = 0; g < 8; g++) acc[g] += qs[g][k] * w;
    }
#pragma unroll 4
    for (int k = 0; k < 64; k++) {
        float w = __ldg(&wh[k]);
#pragma unroll
        for (int g = 0; g < 8; g++) acc[g] += hs[g][k] * w;
    }
#pragma unroll
    for (int g = 0; g < 8; g++) gsm[g][j] = acc[g];
    __syncthreads();

    for (int idx = tid; idx < 8 * 64; idx += 256) {
        int g = idx >> 6, f = idx & 63;
        int b = b0 + g;
        if (b >= B_) continue;
        float ig = sigm(gsm[g][f]);
        float fg = sigm(gsm[g][64 + f]);
        float gg = tanhf(gsm[g][128 + f]);
        float og = sigm(gsm[g][192 + f]);
        float c = fg * g_cl[b * 64 + f] + ig * gg;
        float h = og * tanhf(c);
        g_cl[b * 64 + f] = c;
        g_hl[b * 64 + f] = h;
    }
}

// ---------------- attention (segment softmax + weighted sum) per graph ----------------
__global__ void attn_kernel() {
    int b = blockIdx.x;
    int tid = threadIdx.x;   // 128 threads
    __shared__ float qv[64];
    __shared__ float red[128];
    if (tid < 64) qv[tid] = g_hl[b * 64 + tid];
    __syncthreads();

    int s = g_ptr[b], eend = g_ptr[b + 1];

    float lmax = -INFINITY;
    for (int n = s + tid; n < eend; n += 128) {
        const float4* hr = (const float4*)&g_h[n * 64];
        const float4* qq = (const float4*)qv;
        float d = 0.f;
#pragma unroll
        for (int k = 0; k < 16; k++) {
            float4 a = hr[k], c = qq[k];
            d += a.x * c.x + a.y * c.y + a.z * c.z + a.w * c.w;
        }
        g_e[n] = d;
        lmax = fmaxf(lmax, d);
    }
    red[tid] = lmax;
    __syncthreads();
    for (int o = 64; o > 0; o >>= 1) {
        if (tid < o) red[tid] = fmaxf(red[tid], red[tid + o]);
        __syncthreads();
    }
    float mmax = red[0];
    __syncthreads();

    float lsum = 0.f;
    for (int n = s + tid; n < eend; n += 128) {
        float a = expf(g_e[n] - mmax);
        g_e[n] = a;
        lsum += a;
    }
    red[tid] = lsum;
    __syncthreads();
    for (int o = 64; o > 0; o >>= 1) {
        if (tid < o) red[tid] += red[tid + o];
        __syncthreads();
    }
    float den = red[0];
    __syncthreads();

    if (tid < 64) {
        float accr = 0.f;
        for (int n = s; n < eend; n++) accr += g_e[n] * g_h[n * 64 + tid];
        float rv = (den > 0.f) ? accr / den : 0.f;
        g_qstar[b * 128 + tid] = qv[tid];
        g_qstar[b * 128 + 64 + tid] = rv;
    }
}

// ---------------- output head ----------------
__global__ void out_head_kernel(const float* __restrict__ Wo1, const float* __restrict__ bo1,
                                const float* __restrict__ Wo2, const float* __restrict__ bo2,
                                float* __restrict__ out) {
    int b = blockIdx.x;
    int j = threadIdx.x;   // 64
    __shared__ float qs[128];
    __shared__ float hr[64];
    qs[j] = g_qstar[b * 128 + j];
    qs[64 + j] = g_qstar[b * 128 + 64 + j];
    __syncthreads();
    float acc = bo1[j];
    const float* wr = Wo1 + j * 128;
#pragma unroll 4
    for (int k = 0; k < 128; k++) acc += qs[k] * wr[k];
    acc = fmaxf(acc, 0.f) * Wo2[j];
    hr[j] = acc;
    __syncthreads();
    for (int o = 32; o > 0; o >>= 1) {
        if (j < o) hr[j] += hr[j + o];
        __syncthreads();
    }
    if (j == 0) out[b] = hr[0] + bo2[0];
}

// ---------------- host launch ----------------
extern "C" void kernel_launch(void* const* d_in, const int* in_sizes, int n_in,
                              void* d_out, int out_size) {
    const float* x      = (const float*)d_in[0];
    const float* eattr  = (const float*)d_in[1];
    const float* W_in   = (const float*)d_in[2];
    const float* b_in   = (const float*)d_in[3];
    const float* W_e1   = (const float*)d_in[4];
    const float* b_e1   = (const float*)d_in[5];
    const float* W_e2   = (const float*)d_in[6];
    const float* b_e2   = (const float*)d_in[7];
    const float* b_conv = (const float*)d_in[8];
    const float* W_ih   = (const float*)d_in[9];
    const float* b_ih   = (const float*)d_in[10];
    const float* W_hh   = (const float*)d_in[11];
    const float* b_hh   = (const float*)d_in[12];
    const float* W_ih_l = (const float*)d_in[13];
    const float* b_ih_l = (const float*)d_in[14];
    const float* W_hh_l = (const float*)d_in[15];
    const float* b_hh_l = (const float*)d_in[16];
    const float* W_o1   = (const float*)d_in[17];
    const float* b_o1   = (const float*)d_in[18];
    const float* W_o2   = (const float*)d_in[19];
    const float* b_o2   = (const float*)d_in[20];
    const void*  eidx   = d_in[21];
    const void*  batch  = d_in[22];
    float* out = (float*)d_out;

    static bool attr_set = false;
    if (!attr_set) {
        cudaFuncSetAttribute(msg_mma_kernel,
                             cudaFuncAttributeMaxDynamicSharedMemorySize, MS_TOT);
        attr_set = true;
    }

    // preprocessing
    detect_kernel<<<1, 32>>>(eidx, batch);
    convert_kernel<<<(E_ + 255) / 256, 256>>>(eidx, batch);
    init_zero_kernel<<<(3 * N_ * D_ + 255) / 256, 256>>>();
    counts_kernel<<<(E_ + 255) / 256, 256>>>();
    scan_ptr_kernel<<<1, 32>>>();

    // encoders (fused, with bf16 split of r) + W_e2 split
    encoders_kernel<<<((N_ + E_) * D_ + 255) / 256, 256>>>(x, W_in, b_in, eattr, W_e1, b_e1);
    w2split_kernel<<<(DD_ * D_ + 255) / 256, 256>>>(W_e2);

    // 3 message-passing + GRU iterations (fused msg GEMM, no ew tensor)
    int nblk = (E_ + 63) / 64;
    for (int it = 0; it < 3; it++) {
        msg_mma_kernel<<<nblk, 128, MS_TOT>>>(b_e2, it);
        gru_kernel<<<(N_ + 15) / 16, 192>>>(W_ih, b_ih, W_hh, b_hh, b_conv, it);
    }

    // Set2Set (q_star/hl/cl pre-zeroed)
    for (int it = 0; it < 3; it++) {
        lstm_kernel<<<(B_ + 7) / 8, 256>>>(W_ih_l, b_ih_l, W_hh_l, b_hh_l);
        attn_kernel<<<B_, 128>>>();
    }

    out_head_kernel<<<B_, 64>>>(W_o1, b_o1, W_o2, b_o2, out);
}

// round 6
// speedup vs baseline: 1.0002x; 1.0002x over previous
#include <cuda_runtime.h>
#include <cuda_bf16.h>
#include <math.h>
#include <stdint.h>

#define N_  10000
#define E_  20000
#define B_  400
#define ND_ 32
#define ED_ 16
#define D_  64
#define DD_ 4096   // D*D

// ---------------- scratch (device globals; no cudaMalloc allowed) ----------------
__device__ float g_h[N_ * D_];            // node hidden / out
__device__ __nv_bfloat16 g_rhi[E_ * D_];  // edge MLP hidden, bf16 hi
__device__ __nv_bfloat16 g_rlo[E_ * D_];  // bf16 lo (residual)
__device__ __nv_bfloat16 g_w2hi[DD_ * D_]; // W_e2 split hi [4096][64]
__device__ __nv_bfloat16 g_w2lo[DD_ * D_];
__device__ float g_agg[3 * N_ * D_];      // scatter accumulators (one per iteration)
__device__ float g_cnt[N_];               // dst degree
__device__ int   g_src[E_], g_dst[E_], g_batch[N_];
__device__ int   g_flags[2];              // [0]=edge_index is int64, [1]=batch is int64
__device__ int   g_gcnt[B_];
__device__ int   g_ptr[B_ + 1];
__device__ float g_qstar[B_ * 2 * D_];
__device__ float g_hl[B_ * D_];
__device__ float g_cl[B_ * D_];
__device__ float g_e[N_];                 // per-node attention logits / weights

__device__ __forceinline__ float sigm(float x) { return 1.f / (1.f + expf(-x)); }

__device__ __forceinline__ uint32_t smem_u32(const void* p) {
    uint32_t a;
    asm("{ .reg .u64 t; cvta.to.shared.u64 t, %1; cvt.u32.u64 %0, t; }" : "=r"(a) : "l"(p));
    return a;
}
__device__ __forceinline__ void cp16(uint32_t dst, const void* src) {
    asm volatile("cp.async.cg.shared.global [%0], [%1], 16;" :: "r"(dst), "l"(src));
}

// ---------------- dtype detection (int64 vs int32 delivered buffers) ----------------
__global__ void detect_kernel(const void* ei, const void* ba) {
    if (threadIdx.x != 0) return;
    {
        const long long* p = (const long long*)ei;
        int ok = 1;
        for (int i = 0; i < 8; i++) { long long v = p[i]; if (v < 0 || v >= N_) ok = 0; }
        for (int i = 0; i < 8; i++) { long long v = p[2 * E_ / 2 - 8 + i]; if (v < 0 || v >= N_) ok = 0; }
        g_flags[0] = ok;
    }
    {
        const long long* p = (const long long*)ba;
        int ok = 1;
        for (int i = 0; i < 8; i++) { long long v = p[i]; if (v < 0 || v >= B_) ok = 0; }
        for (int i = 0; i < 8; i++) { long long v = p[N_ / 2 - 8 + i]; if (v < 0 || v >= B_) ok = 0; }
        g_flags[1] = ok;
    }
}

__global__ void convert_kernel(const void* ei, const void* ba) {
    int i = blockIdx.x * blockDim.x + threadIdx.x;
    if (i < E_) {
        if (g_flags[0]) {
            const long long* p = (const long long*)ei;
            g_src[i] = (int)p[i];
            g_dst[i] = (int)p[E_ + i];
        } else {
            const int* p = (const int*)ei;
            g_src[i] = p[i];
            g_dst[i] = p[E_ + i];
        }
    }
    if (i < N_) {
        if (g_flags[1]) {
            const long long* p = (const long long*)ba;
            g_batch[i] = (int)p[i];
        } else {
            const int* p = (const int*)ba;
            g_batch[i] = p[i];
        }
    }
}

// ---------------- fused zero init ----------------
__global__ void init_zero_kernel() {
    int i = blockIdx.x * blockDim.x + threadIdx.x;
    int stride = gridDim.x * blockDim.x;
    for (int j = i; j < 3 * N_ * D_; j += stride) g_agg[j] = 0.f;
    if (i < N_) g_cnt[i] = 0.f;
    if (i < B_) g_gcnt[i] = 0;
    if (i < B_ * 2 * D_) g_qstar[i] = 0.f;
    if (i < B_ * D_) { g_hl[i] = 0.f; g_cl[i] = 0.f; }
}

__global__ void counts_kernel() {
    int i = blockIdx.x * blockDim.x + threadIdx.x;
    if (i < E_) atomicAdd(&g_cnt[g_dst[i]], 1.0f);
    if (i < N_) atomicAdd(&g_gcnt[g_batch[i]], 1);
}

__global__ void scan_ptr_kernel() {
    if (threadIdx.x != 0) return;
    int acc = 0;
    g_ptr[0] = 0;
    for (int b = 0; b < B_; b++) { acc += g_gcnt[b]; g_ptr[b + 1] = acc; }
}

// ---------------- W_e2 split to bf16 hi/lo ----------------
__global__ void w2split_kernel(const float* __restrict__ W) {
    int i = blockIdx.x * blockDim.x + threadIdx.x;
    if (i >= DD_ * D_) return;
    float w = W[i];
    __nv_bfloat16 hi = __float2bfloat16(w);
    __nv_bfloat16 lo = __float2bfloat16(w - __bfloat162float(hi));
    g_w2hi[i] = hi;
    g_w2lo[i] = lo;
}

// ---------------- fused encoders: in_linear + edge_hidden(+split) ----------------
__global__ void encoders_kernel(const float* __restrict__ x,
                                const float* __restrict__ W_in, const float* __restrict__ b_in,
                                const float* __restrict__ ea,
                                const float* __restrict__ W_e1, const float* __restrict__ b_e1) {
    int i = blockIdx.x * blockDim.x + threadIdx.x;
    if (i < N_ * D_) {
        int n = i >> 6, f = i & 63;
        float acc = b_in[f];
        const float* xr = x + n * ND_;
        const float* wr = W_in + f * ND_;
#pragma unroll
        for (int k = 0; k < ND_; k++) acc += xr[k] * wr[k];
        g_h[i] = fmaxf(acc, 0.f);
    } else if (i < N_ * D_ + E_ * D_) {
        int j = i - N_ * D_;
        int e = j >> 6, f = j & 63;
        float acc = b_e1[f];
        const float* er = ea + e * ED_;
        const float* wr = W_e1 + f * ED_;
#pragma unroll
        for (int k = 0; k < ED_; k++) acc += er[k] * wr[k];
        float r = fmaxf(acc, 0.f);
        __nv_bfloat16 hi = __float2bfloat16(r);
        __nv_bfloat16 lo = __float2bfloat16(r - __bfloat162float(hi));
        g_rhi[j] = hi;
        g_rlo[j] = lo;
    }
}

// ============ fused NNConv message GEMM (no ew materialization) ============
// Per CTA: 64 edges, 128 threads (4 warps, warp = 16 rows x 64 cols).
// msg[e,f] = sum_d h[src_e,d] * (R[e,:]@W2_d^T)[f]  + (h[src_e,:]@B2)[f]
// Q_d computed on tensor cores (bf16 hi/lo 3-product split, fp32 acc),
// scaled by fp32 h[:,d], accumulated in registers; atomic scatter at end.
#define EWPAD 72     // bf16 row stride (144B): conflict-free ldmatrix phases
#define MS_RHI 0
#define MS_RLO 9216
#define MS_W2  18432                 // 2 bufs x (hi 9216 + lo 9216)
#define MS_HD  55296                 // 64 x 65 fp32 (transposed h, padded)
#define MS_B2  71936                 // 4096 fp32
#define MS_TOT 88320

__device__ __forceinline__ void ldsm4(uint32_t addr, uint32_t* r) {
    asm volatile("ldmatrix.sync.aligned.m8n8.x4.shared.b16 {%0,%1,%2,%3}, [%4];"
                 : "=r"(r[0]), "=r"(r[1]), "=r"(r[2]), "=r"(r[3]) : "r"(addr));
}
__device__ __forceinline__ void mma_bf16(float* c, const uint32_t* a, uint32_t b0, uint32_t b1) {
    asm volatile(
        "mma.sync.aligned.m16n8k16.row.col.f32.bf16.bf16.f32 "
        "{%0,%1,%2,%3}, {%4,%5,%6,%7}, {%8,%9}, {%0,%1,%2,%3};"
        : "+f"(c[0]), "+f"(c[1]), "+f"(c[2]), "+f"(c[3])
        : "r"(a[0]), "r"(a[1]), "r"(a[2]), "r"(a[3]), "r"(b0), "r"(b1));
}

__device__ __forceinline__ void stage_w2(char* smem, uint32_t sb, int buf, int d, int tid) {
    uint32_t bufh = sb + MS_W2 + buf * 18432;
    for (int i = tid; i < 512; i += 128) {
        int row = i >> 3, k8 = i & 7;
        uint32_t off = (uint32_t)(row * EWPAD + k8 * 8) * 2;
        size_t gi = (size_t)(d * 64 + row) * 64 + k8 * 8;
        cp16(bufh + off, &g_w2hi[gi]);
        cp16(bufh + 9216 + off, &g_w2lo[gi]);
    }
    asm volatile("cp.async.commit_group;" ::: "memory");
}

__global__ void __launch_bounds__(128) msg_mma_kernel(const float* __restrict__ b2, int it) {
    extern __shared__ char smem[];
    uint32_t sb = smem_u32(smem);
    int tid = threadIdx.x;
    int e0 = blockIdx.x * 64;
    int w = tid >> 5, lane = tid & 31;
    int r8 = lane & 7, q = lane >> 3;
    int g = lane >> 2, qq = lane & 3;

    // stage R hi/lo (padded)
    for (int i = tid; i < 512; i += 128) {
        int row = i >> 3, k8 = i & 7;
        int e = e0 + row;
        uint32_t off = (uint32_t)(row * EWPAD + k8 * 8) * 2;
        uint4 vh = make_uint4(0, 0, 0, 0), vl = make_uint4(0, 0, 0, 0);
        if (e < E_) {
            vh = *(const uint4*)&g_rhi[e * 64 + k8 * 8];
            vl = *(const uint4*)&g_rlo[e * 64 + k8 * 8];
        }
        *(uint4*)(smem + MS_RHI + off) = vh;
        *(uint4*)(smem + MS_RLO + off) = vl;
    }
    // stage HD (transposed h gather) + B2
    for (int i = tid; i < 4096; i += 128) {
        int e = i >> 6, d = i & 63;
        int ee = e0 + e;
        float v = (ee < E_) ? g_h[g_src[ee] * 64 + d] : 0.f;
        *(float*)(smem + MS_HD + (d * 65 + e) * 4) = v;
        *(float*)(smem + MS_B2 + i * 4) = b2[i];
    }
    // prefetch W2 chunk d=0
    stage_w2(smem, sb, 0, 0, tid);
    __syncthreads();

    // A fragments from R (persist for whole d-loop)
    int a_row = ((q & 1) ? 8 : 0) + r8;
    int a_col = (q >= 2) ? 8 : 0;
    int b_row = ((q >= 2) ? 8 : 0) + r8;
    int b_col = (q & 1) ? 8 : 0;

    uint32_t arhi[4][4], arlo[4][4];
#pragma unroll
    for (int k0 = 0; k0 < 4; k0++) {
        uint32_t ad = sb + MS_RHI + (uint32_t)((w * 16 + a_row) * EWPAD + k0 * 16 + a_col) * 2;
        ldsm4(ad, arhi[k0]);
        ldsm4(ad + 9216, arlo[k0]);
    }

    int el0 = w * 16 + g;   // local row of c[.][0,1]; +8 for c[.][2,3]
    float msg[8][4];
#pragma unroll
    for (int n = 0; n < 8; n++)
#pragma unroll
        for (int j = 0; j < 4; j++) msg[n][j] = 0.f;

    // bias term: msg += h @ B2  (fp32)
#pragma unroll 2
    for (int d = 0; d < 64; d++) {
        float hv0 = *(const float*)(smem + MS_HD + (d * 65 + el0) * 4);
        float hv1 = *(const float*)(smem + MS_HD + (d * 65 + el0 + 8) * 4);
#pragma unroll
        for (int n = 0; n < 8; n++) {
            float2 bb = *(const float2*)(smem + MS_B2 + (d * 64 + n * 8 + qq * 2) * 4);
            msg[n][0] += hv0 * bb.x;
            msg[n][1] += hv0 * bb.y;
            msg[n][2] += hv1 * bb.x;
            msg[n][3] += hv1 * bb.y;
        }
    }

    // main d-loop: Q_d = R @ W2_d^T on tensor cores; msg += h[:,d] * Q_d
    for (int d = 0; d < 64; d++) {
        if (d + 1 < 64) stage_w2(smem, sb, (d + 1) & 1, d + 1, tid);
        if (d + 1 < 64) asm volatile("cp.async.wait_group 1;" ::: "memory");
        else            asm volatile("cp.async.wait_group 0;" ::: "memory");
        __syncthreads();

        uint32_t bufh = sb + MS_W2 + (uint32_t)((d & 1) * 18432);
        float qd[8][4];
#pragma unroll
        for (int n = 0; n < 8; n++)
#pragma unroll
            for (int j = 0; j < 4; j++) qd[n][j] = 0.f;

#pragma unroll
        for (int k0 = 0; k0 < 4; k0++) {
#pragma unroll
            for (int p = 0; p < 4; p++) {
                uint32_t bd = bufh + (uint32_t)((p * 16 + b_row) * EWPAD + k0 * 16 + b_col) * 2;
                uint32_t bhi[4], blo[4];
                ldsm4(bd, bhi);
                ldsm4(bd + 9216, blo);
#pragma unroll
                for (int nn = 0; nn < 2; nn++) {
                    int n = p * 2 + nn, s = nn * 2;
                    mma_bf16(qd[n], arhi[k0], bhi[s], bhi[s + 1]);
                    mma_bf16(qd[n], arhi[k0], blo[s], blo[s + 1]);
                    mma_bf16(qd[n], arlo[k0], bhi[s], bhi[s + 1]);
                }
            }
        }
        float hv0 = *(const float*)(smem + MS_HD + (d * 65 + el0) * 4);
        float hv1 = *(const float*)(smem + MS_HD + (d * 65 + el0 + 8) * 4);
#pragma unroll
        for (int n = 0; n < 8; n++) {
            msg[n][0] += hv0 * qd[n][0];
            msg[n][1] += hv0 * qd[n][1];
            msg[n][2] += hv1 * qd[n][2];
            msg[n][3] += hv1 * qd[n][3];
        }
        __syncthreads();
    }

    // scatter to agg[dst]
    float* agg = &g_agg[(size_t)it * N_ * D_];
    int ge0 = e0 + el0, ge1 = e0 + el0 + 8;
    int dst0 = (ge0 < E_) ? g_dst[ge0] : -1;
    int dst1 = (ge1 < E_) ? g_dst[ge1] : -1;
#pragma unroll
    for (int n = 0; n < 8; n++) {
        int col = n * 8 + qq * 2;
        if (dst0 >= 0) {
            atomicAdd(&agg[dst0 * 64 + col], msg[n][0]);
            atomicAdd(&agg[dst0 * 64 + col + 1], msg[n][1]);
        }
        if (dst1 >= 0) {
            atomicAdd(&agg[dst1 * 64 + col], msg[n][2]);
            atomicAdd(&agg[dst1 * 64 + col + 1], msg[n][3]);
        }
    }
}

// ---------------- GRU update over node tiles of 16 ----------------
__global__ void __launch_bounds__(192) gru_kernel(const float* __restrict__ Wih,
                                                  const float* __restrict__ bih,
                                                  const float* __restrict__ Whh,
                                                  const float* __restrict__ bhh,
                                                  const float* __restrict__ bconv,
                                                  int it) {
    __shared__ float Msm[16][64];
    __shared__ float Hsm[16][64];
    __shared__ float GI[16][192];
    __shared__ float GH[16][192];
    int n0 = blockIdx.x * 16;
    int tid = threadIdx.x;
    const float* agg = &g_agg[(size_t)it * N_ * D_];

    for (int idx = tid; idx < 16 * 64; idx += 192) {
        int m = idx >> 6, k = idx & 63;
        int n = n0 + m;
        if (n < N_) {
            float cdeg = fmaxf(g_cnt[n], 1.0f);
            Msm[m][k] = fmaxf(agg[n * 64 + k] / cdeg + bconv[k], 0.f);
            Hsm[m][k] = g_h[n * 64 + k];
        } else {
            Msm[m][k] = 0.f;
            Hsm[m][k] = 0.f;
        }
    }
    __syncthreads();

    float wih[64], whh[64];
    const float* wi = Wih + tid * 64;
    const float* wh = Whh + tid * 64;
#pragma unroll
    for (int k = 0; k < 64; k++) { wih[k] = __ldg(&wi[k]); whh[k] = __ldg(&wh[k]); }
    float bi = bih[tid], bh = bhh[tid];

#pragma unroll 4
    for (int m = 0; m < 16; m++) {
        float ai = bi, ah = bh;
#pragma unroll
        for (int k = 0; k < 64; k++) {
            ai += Msm[m][k] * wih[k];
            ah += Hsm[m][k] * whh[k];
        }
        GI[m][tid] = ai;
        GH[m][tid] = ah;
    }
    __syncthreads();

    for (int idx = tid; idx < 16 * 64; idx += 192) {
        int m = idx >> 6, f = idx & 63;
        int n = n0 + m;
        if (n >= N_) continue;
        float r = sigm(GI[m][f] + GH[m][f]);
        float z = sigm(GI[m][64 + f] + GH[m][64 + f]);
        float nn = tanhf(GI[m][128 + f] + r * GH[m][128 + f]);
        float hnew = (1.f - z) * nn + z * Hsm[m][f];
        g_h[n * 64 + f] = hnew;
    }
}

// ---------------- Set2Set LSTM cell (8 graphs per 256-thread block) ----------------
__global__ void lstm_kernel(const float* __restrict__ Wih, const float* __restrict__ bih,
                            const float* __restrict__ Whh, const float* __restrict__ bhh) {
    __shared__ float qs[8][128];
    __shared__ float hs[8][64];
    __shared__ float gsm[8][256];
    int b0 = blockIdx.x * 8;
    int tid = threadIdx.x;

    for (int idx = tid; idx < 8 * 128; idx += 256) {
        int g = idx >> 7, k = idx & 127;
        int b = b0 + g;
        qs[g][k] = (b < B_) ? g_qstar[b * 128 + k] : 0.f;
    }
    for (int idx = tid; idx < 8 * 64; idx += 256) {
        int g = idx >> 6, k = idx & 63;
        int b = b0 + g;
        hs[g][k] = (b < B_) ? g_hl[b * 64 + k] : 0.f;
    }
    __syncthreads();

    int j = tid;
    float acc[8];
    float bsum = bih[j] + bhh[j];
#pragma unroll
    for (int g = 0; g < 8; g++) acc[g] = bsum;
    const float* wi = Wih + j * 128;
    const float* wh = Whh + j * 64;
#pragma unroll 4
    for (int k = 0; k < 128; k++) {
        float w = __ldg(&wi[k]);
#pragma unroll
        for (int g = 0; g < 8; g++) acc[g] += qs[g][k] * w;
    }
#pragma unroll 4
    for (int k = 0; k < 64; k++) {
        float w = __ldg(&wh[k]);
#pragma unroll
        for (int g = 0; g < 8; g++) acc[g] += hs[g][k] * w;
    }
#pragma unroll
    for (int g = 0; g < 8; g++) gsm[g][j] = acc[g];
    __syncthreads();

    for (int idx = tid; idx < 8 * 64; idx += 256) {
        int g = idx >> 6, f = idx & 63;
        int b = b0 + g;
        if (b >= B_) continue;
        float ig = sigm(gsm[g][f]);
        float fg = sigm(gsm[g][64 + f]);
        float gg = tanhf(gsm[g][128 + f]);
        float og = sigm(gsm[g][192 + f]);
        float c = fg * g_cl[b * 64 + f] + ig * gg;
        float h = og * tanhf(c);
        g_cl[b * 64 + f] = c;
        g_hl[b * 64 + f] = h;
    }
}

// ---------------- attention (segment softmax + weighted sum) per graph ----------------
__global__ void attn_kernel() {
    int b = blockIdx.x;
    int tid = threadIdx.x;   // 128 threads
    __shared__ float qv[64];
    __shared__ float red[128];
    if (tid < 64) qv[tid] = g_hl[b * 64 + tid];
    __syncthreads();

    int s = g_ptr[b], eend = g_ptr[b + 1];

    float lmax = -INFINITY;
    for (int n = s + tid; n < eend; n += 128) {
        const float4* hr = (const float4*)&g_h[n * 64];
        const float4* qq = (const float4*)qv;
        float d = 0.f;
#pragma unroll
        for (int k = 0; k < 16; k++) {
            float4 a = hr[k], c = qq[k];
            d += a.x * c.x + a.y * c.y + a.z * c.z + a.w * c.w;
        }
        g_e[n] = d;
        lmax = fmaxf(lmax, d);
    }
    red[tid] = lmax;
    __syncthreads();
    for (int o = 64; o > 0; o >>= 1) {
        if (tid < o) red[tid] = fmaxf(red[tid], red[tid + o]);
        __syncthreads();
    }
    float mmax = red[0];
    __syncthreads();

    float lsum = 0.f;
    for (int n = s + tid; n < eend; n += 128) {
        float a = expf(g_e[n] - mmax);
        g_e[n] = a;
        lsum += a;
    }
    red[tid] = lsum;
    __syncthreads();
    for (int o = 64; o > 0; o >>= 1) {
        if (tid < o) red[tid] += red[tid + o];
        __syncthreads();
    }
    float den = red[0];
    __syncthreads();

    if (tid < 64) {
        float accr = 0.f;
        for (int n = s; n < eend; n++) accr += g_e[n] * g_h[n * 64 + tid];
        float rv = (den > 0.f) ? accr / den : 0.f;
        g_qstar[b * 128 + tid] = qv[tid];
        g_qstar[b * 128 + 64 + tid] = rv;
    }
}

// ---------------- output head ----------------
__global__ void out_head_kernel(const float* __restrict__ Wo1, const float* __restrict__ bo1,
                                const float* __restrict__ Wo2, const float* __restrict__ bo2,
                                float* __restrict__ out) {
    int b = blockIdx.x;
    int j = threadIdx.x;   // 64
    __shared__ float qs[128];
    __shared__ float hr[64];
    qs[j] = g_qstar[b * 128 + j];
    qs[64 + j] = g_qstar[b * 128 + 64 + j];
    __syncthreads();
    float acc = bo1[j];
    const float* wr = Wo1 + j * 128;
#pragma unroll 4
    for (int k = 0; k < 128; k++) acc += qs[k] * wr[k];
    acc = fmaxf(acc, 0.f) * Wo2[j];
    hr[j] = acc;
    __syncthreads();
    for (int o = 32; o > 0; o >>= 1) {
        if (j < o) hr[j] += hr[j + o];
        __syncthreads();
    }
    if (j == 0) out[b] = hr[0] + bo2[0];
}

// ---------------- host launch ----------------
extern "C" void kernel_launch(void* const* d_in, const int* in_sizes, int n_in,
                              void* d_out, int out_size) {
    const float* x      = (const float*)d_in[0];
    const float* eattr  = (const float*)d_in[1];
    const float* W_in   = (const float*)d_in[2];
    const float* b_in   = (const float*)d_in[3];
    const float* W_e1   = (const float*)d_in[4];
    const float* b_e1   = (const float*)d_in[5];
    const float* W_e2   = (const float*)d_in[6];
    const float* b_e2   = (const float*)d_in[7];
    const float* b_conv = (const float*)d_in[8];
    const float* W_ih   = (const float*)d_in[9];
    const float* b_ih   = (const float*)d_in[10];
    const float* W_hh   = (const float*)d_in[11];
    const float* b_hh   = (const float*)d_in[12];
    const float* W_ih_l = (const float*)d_in[13];
    const float* b_ih_l = (const float*)d_in[14];
    const float* W_hh_l = (const float*)d_in[15];
    const float* b_hh_l = (const float*)d_in[16];
    const float* W_o1   = (const float*)d_in[17];
    const float* b_o1   = (const float*)d_in[18];
    const float* W_o2   = (const float*)d_in[19];
    const float* b_o2   = (const float*)d_in[20];
    const void*  eidx   = d_in[21];
    const void*  batch  = d_in[22];
    float* out = (float*)d_out;

    static bool attr_set = false;
    if (!attr_set) {
        cudaFuncSetAttribute(msg_mma_kernel,
                             cudaFuncAttributeMaxDynamicSharedMemorySize, MS_TOT);
        attr_set = true;
    }

    // preprocessing
    detect_kernel<<<1, 32>>>(eidx, batch);
    convert_kernel<<<(E_ + 255) / 256, 256>>>(eidx, batch);
    init_zero_kernel<<<(3 * N_ * D_ + 255) / 256, 256>>>();
    counts_kernel<<<(E_ + 255) / 256, 256>>>();
    scan_ptr_kernel<<<1, 32>>>();

    // encoders (fused, with bf16 split of r) + W_e2 split
    encoders_kernel<<<((N_ + E_) * D_ + 255) / 256, 256>>>(x, W_in, b_in, eattr, W_e1, b_e1);
    w2split_kernel<<<(DD_ * D_ + 255) / 256, 256>>>(W_e2);

    // 3 message-passing + GRU iterations (fused msg GEMM, no ew tensor)
    int nblk = (E_ + 63) / 64;
    for (int it = 0; it < 3; it++) {
        msg_mma_kernel<<<nblk, 128, MS_TOT>>>(b_e2, it);
        gru_kernel<<<(N_ + 15) / 16, 192>>>(W_ih, b_ih, W_hh, b_hh, b_conv, it);
    }

    // Set2Set (q_star/hl/cl pre-zeroed)
    for (int it = 0; it < 3; it++) {
        lstm_kernel<<<(B_ + 7) / 8, 256>>>(W_ih_l, b_ih_l, W_hh_l, b_hh_l);
        attn_kernel<<<B_, 128>>>();
    }

    out_head_kernel<<<B_, 64>>>(W_o1, b_o1, W_o2, b_o2, out);
}

// round 7
// speedup vs baseline: 1.0995x; 1.0993x over previous
#include <cuda_runtime.h>
#include <cuda_bf16.h>
#include <math.h>
#include <stdint.h>

#define N_  10000
#define E_  20000
#define B_  400
#define ND_ 32
#define ED_ 16
#define D_  64
#define DD_ 4096   // D*D

// ---------------- scratch (device globals; no cudaMalloc allowed) ----------------
__device__ float g_h[N_ * D_];            // node hidden / out
__device__ __nv_bfloat16 g_rhi[E_ * D_];  // edge MLP hidden, bf16 hi
__device__ __nv_bfloat16 g_rlo[E_ * D_];  // bf16 lo (residual)
__device__ __nv_bfloat16 g_w2hi[DD_ * D_]; // W_e2 split hi [4096][64]
__device__ __nv_bfloat16 g_w2lo[DD_ * D_];
__device__ float g_ew[(size_t)E_ * DD_];  // edge-conditioned weights [E,64,64] (327MB)
__device__ float g_agg[3 * N_ * D_];      // scatter accumulators (one per iteration)
__device__ float g_cnt[N_];               // dst degree
__device__ int   g_src[E_], g_dst[E_], g_batch[N_];
__device__ int   g_flags[2];              // [0]=edge_index is int64, [1]=batch is int64
__device__ int   g_gcnt[B_];
__device__ int   g_ptr[B_ + 1];
__device__ float g_qstar[B_ * 2 * D_];
__device__ float g_hl[B_ * D_];
__device__ float g_cl[B_ * D_];
__device__ float g_e[N_];                 // per-node attention logits / weights

__device__ __forceinline__ float sigm(float x) { return 1.f / (1.f + expf(-x)); }

__device__ __forceinline__ uint32_t smem_u32(const void* p) {
    uint32_t a;
    asm("{ .reg .u64 t; cvta.to.shared.u64 t, %1; cvt.u32.u64 %0, t; }" : "=r"(a) : "l"(p));
    return a;
}
__device__ __forceinline__ void cp16(uint32_t dst, const void* src) {
    asm volatile("cp.async.cg.shared.global [%0], [%1], 16;" :: "r"(dst), "l"(src));
}

// ---------------- dtype detection (int64 vs int32 delivered buffers) ----------------
__global__ void detect_kernel(const void* ei, const void* ba) {
    if (threadIdx.x != 0) return;
    {
        const long long* p = (const long long*)ei;
        int ok = 1;
        for (int i = 0; i < 8; i++) { long long v = p[i]; if (v < 0 || v >= N_) ok = 0; }
        for (int i = 0; i < 8; i++) { long long v = p[2 * E_ / 2 - 8 + i]; if (v < 0 || v >= N_) ok = 0; }
        g_flags[0] = ok;
    }
    {
        const long long* p = (const long long*)ba;
        int ok = 1;
        for (int i = 0; i < 8; i++) { long long v = p[i]; if (v < 0 || v >= B_) ok = 0; }
        for (int i = 0; i < 8; i++) { long long v = p[N_ / 2 - 8 + i]; if (v < 0 || v >= B_) ok = 0; }
        g_flags[1] = ok;
    }
}

__global__ void convert_kernel(const void* ei, const void* ba) {
    int i = blockIdx.x * blockDim.x + threadIdx.x;
    if (i < E_) {
        if (g_flags[0]) {
            const long long* p = (const long long*)ei;
            g_src[i] = (int)p[i];
            g_dst[i] = (int)p[E_ + i];
        } else {
            const int* p = (const int*)ei;
            g_src[i] = p[i];
            g_dst[i] = p[E_ + i];
        }
    }
    if (i < N_) {
        if (g_flags[1]) {
            const long long* p = (const long long*)ba;
            g_batch[i] = (int)p[i];
        } else {
            const int* p = (const int*)ba;
            g_batch[i] = p[i];
        }
    }
}

// ---------------- fused zero init ----------------
__global__ void init_zero_kernel() {
    int i = blockIdx.x * blockDim.x + threadIdx.x;
    int stride = gridDim.x * blockDim.x;
    for (int j = i; j < 3 * N_ * D_; j += stride) g_agg[j] = 0.f;
    if (i < N_) g_cnt[i] = 0.f;
    if (i < B_) g_gcnt[i] = 0;
    if (i < B_ * 2 * D_) g_qstar[i] = 0.f;
    if (i < B_ * D_) { g_hl[i] = 0.f; g_cl[i] = 0.f; }
}

__global__ void counts_kernel() {
    int i = blockIdx.x * blockDim.x + threadIdx.x;
    if (i < E_) atomicAdd(&g_cnt[g_dst[i]], 1.0f);
    if (i < N_) atomicAdd(&g_gcnt[g_batch[i]], 1);
}

__global__ void scan_ptr_kernel() {
    if (threadIdx.x != 0) return;
    int acc = 0;
    g_ptr[0] = 0;
    for (int b = 0; b < B_; b++) { acc += g_gcnt[b]; g_ptr[b + 1] = acc; }
}

// ---------------- W_e2 split to bf16 hi/lo ----------------
__global__ void w2split_kernel(const float* __restrict__ W) {
    int i = blockIdx.x * blockDim.x + threadIdx.x;
    if (i >= DD_ * D_) return;
    float w = W[i];
    __nv_bfloat16 hi = __float2bfloat16(w);
    __nv_bfloat16 lo = __float2bfloat16(w - __bfloat162float(hi));
    g_w2hi[i] = hi;
    g_w2lo[i] = lo;
}

// ---------------- fused encoders: in_linear + edge_hidden(+split) ----------------
__global__ void encoders_kernel(const float* __restrict__ x,
                                const float* __restrict__ W_in, const float* __restrict__ b_in,
                                const float* __restrict__ ea,
                                const float* __restrict__ W_e1, const float* __restrict__ b_e1) {
    int i = blockIdx.x * blockDim.x + threadIdx.x;
    if (i < N_ * D_) {
        int n = i >> 6, f = i & 63;
        float acc = b_in[f];
        const float* xr = x + n * ND_;
        const float* wr = W_in + f * ND_;
#pragma unroll
        for (int k = 0; k < ND_; k++) acc += xr[k] * wr[k];
        g_h[i] = fmaxf(acc, 0.f);
    } else if (i < N_ * D_ + E_ * D_) {
        int j = i - N_ * D_;
        int e = j >> 6, f = j & 63;
        float acc = b_e1[f];
        const float* er = ea + e * ED_;
        const float* wr = W_e1 + f * ED_;
#pragma unroll
        for (int k = 0; k < ED_; k++) acc += er[k] * wr[k];
        float r = fmaxf(acc, 0.f);
        __nv_bfloat16 hi = __float2bfloat16(r);
        __nv_bfloat16 lo = __float2bfloat16(r - __bfloat162float(hi));
        g_rhi[j] = hi;
        g_rlo[j] = lo;
    }
}

// ============ ew GEMM via mma.sync bf16-split: g_ew = R @ W_e2^T + b_e2 ============
// CTA tile 128(M edges) x 128(N cols), K=64. 8 warps, warp tile 32x64.
// Operands pre-split to bf16 hi/lo in global; 3-product split, fp32 accum.
#define EWPAD 72     // bf16 row stride (144B): conflict-free ldmatrix phases
#define SM_AHI 0
#define SM_ALO (SM_AHI + 128 * EWPAD * 2)   // 18432
#define SM_BHI (SM_ALO + 128 * EWPAD * 2)   // 36864
#define SM_BLO (SM_BHI + 128 * EWPAD * 2)   // 55296
#define SM_TOTAL (SM_BLO + 128 * EWPAD * 2) // 73728

__device__ __forceinline__ void ldsm4(uint32_t addr, uint32_t* r) {
    asm volatile("ldmatrix.sync.aligned.m8n8.x4.shared.b16 {%0,%1,%2,%3}, [%4];"
                 : "=r"(r[0]), "=r"(r[1]), "=r"(r[2]), "=r"(r[3]) : "r"(addr));
}
__device__ __forceinline__ void mma_bf16(float* c, const uint32_t* a, uint32_t b0, uint32_t b1) {
    asm volatile(
        "mma.sync.aligned.m16n8k16.row.col.f32.bf16.bf16.f32 "
        "{%0,%1,%2,%3}, {%4,%5,%6,%7}, {%8,%9}, {%0,%1,%2,%3};"
        : "+f"(c[0]), "+f"(c[1]), "+f"(c[2]), "+f"(c[3])
        : "r"(a[0]), "r"(a[1]), "r"(a[2]), "r"(a[3]), "r"(b0), "r"(b1));
}

__global__ void __launch_bounds__(256) ew_mma_kernel(const float* __restrict__ bias) {
    extern __shared__ char smem[];
    uint32_t sb = smem_u32(smem);
    int tid = threadIdx.x;
    int e0 = blockIdx.y * 128;
    int c0 = blockIdx.x * 128;

    // stage A (128 edges x 64 k, hi/lo) via cp.async; zero-fill tail edges
    for (int i = tid; i < 128 * 8; i += 256) {
        int row = i >> 3, k8 = i & 7;
        int e = e0 + row;
        uint32_t off = (uint32_t)(row * EWPAD + k8 * 8) * 2;
        if (e < E_) {
            cp16(sb + SM_AHI + off, &g_rhi[e * 64 + k8 * 8]);
            cp16(sb + SM_ALO + off, &g_rlo[e * 64 + k8 * 8]);
        } else {
            *(uint4*)(smem + SM_AHI + off) = make_uint4(0, 0, 0, 0);
            *(uint4*)(smem + SM_ALO + off) = make_uint4(0, 0, 0, 0);
        }
    }
    // stage B (128 cols x 64 k, hi/lo)
    for (int i = tid; i < 128 * 8; i += 256) {
        int row = i >> 3, k8 = i & 7;
        uint32_t off = (uint32_t)(row * EWPAD + k8 * 8) * 2;
        size_t gi = (size_t)(c0 + row) * 64 + k8 * 8;
        cp16(sb + SM_BHI + off, &g_w2hi[gi]);
        cp16(sb + SM_BLO + off, &g_w2lo[gi]);
    }
    asm volatile("cp.async.commit_group;" ::: "memory");
    asm volatile("cp.async.wait_group 0;" ::: "memory");
    __syncthreads();

    int w = tid >> 5, lane = tid & 31;
    int wm = w & 3, wn = w >> 2;      // warp tile: rows wm*32, cols wn*64
    int r8 = lane & 7, q = lane >> 3;

    int a_row = ((q & 1) ? 8 : 0) + r8;
    int a_col = (q >= 2) ? 8 : 0;
    int b_row = ((q >= 2) ? 8 : 0) + r8;
    int b_col = (q & 1) ? 8 : 0;

    float c[2][8][4];
#pragma unroll
    for (int t = 0; t < 2; t++)
#pragma unroll
        for (int n = 0; n < 8; n++)
#pragma unroll
            for (int j = 0; j < 4; j++) c[t][n][j] = 0.f;

#pragma unroll
    for (int k0 = 0; k0 < 64; k0 += 16) {
        uint32_t ahi[2][4], alo[2][4], bhi[4][4], blo[4][4];
#pragma unroll
        for (int t = 0; t < 2; t++) {
            uint32_t ad = sb + SM_AHI +
                (uint32_t)((wm * 32 + t * 16 + a_row) * EWPAD + k0 + a_col) * 2;
            ldsm4(ad, ahi[t]);
            ldsm4(ad + (SM_ALO - SM_AHI), alo[t]);
        }
#pragma unroll
        for (int p = 0; p < 4; p++) {
            uint32_t bd = sb + SM_BHI +
                (uint32_t)((wn * 64 + p * 16 + b_row) * EWPAD + k0 + b_col) * 2;
            ldsm4(bd, bhi[p]);
            ldsm4(bd + (SM_BLO - SM_BHI), blo[p]);
        }
#pragma unroll
        for (int t = 0; t < 2; t++)
#pragma unroll
            for (int n = 0; n < 8; n++) {
                int p = n >> 1, s = (n & 1) * 2;
                mma_bf16(c[t][n], ahi[t], bhi[p][s], bhi[p][s + 1]);
                mma_bf16(c[t][n], ahi[t], blo[p][s], blo[p][s + 1]);
                mma_bf16(c[t][n], alo[t], bhi[p][s], bhi[p][s + 1]);
            }
    }

    // epilogue: add bias, store fp32
    int g = lane >> 2, qq = lane & 3;
#pragma unroll
    for (int t = 0; t < 2; t++) {
        int row0 = e0 + wm * 32 + t * 16 + g;
#pragma unroll
        for (int n = 0; n < 8; n++) {
            int col = c0 + wn * 64 + n * 8 + qq * 2;
            float bb0 = __ldg(&bias[col]), bb1 = __ldg(&bias[col + 1]);
            if (row0 < E_) {
                float2 v = make_float2(c[t][n][0] + bb0, c[t][n][1] + bb1);
                *(float2*)&g_ew[(size_t)row0 * DD_ + col] = v;
            }
            if (row0 + 8 < E_) {
                float2 v = make_float2(c[t][n][2] + bb0, c[t][n][3] + bb1);
                *(float2*)&g_ew[(size_t)(row0 + 8) * DD_ + col] = v;
            }
        }
    }
}

// ---------------- message + scatter: agg[dst] += ew[e]^T h[src] ----------------
__global__ void msg_kernel(int it) {
    int sub = threadIdx.x >> 6;
    int f = threadIdx.x & 63;
    int e = blockIdx.x * 4 + sub;
    __shared__ float s[4][64];
    int valid = (e < E_);
    int srcn = 0, dstn = 0;
    if (valid) {
        srcn = g_src[e];
        dstn = g_dst[e];
        s[sub][f] = g_h[srcn * 64 + f];
    }
    __syncthreads();
    if (!valid) return;
    const float* w = &g_ew[(size_t)e * DD_ + f];
    const float* sv = s[sub];
    float acc = 0.f;
#pragma unroll
    for (int d = 0; d < 64; d++) acc += sv[d] * w[d * 64];
    atomicAdd(&g_agg[(size_t)it * N_ * D_ + dstn * 64 + f], acc);
}

// ---------------- GRU update over node tiles of 16 ----------------
__global__ void __launch_bounds__(192) gru_kernel(const float* __restrict__ Wih,
                                                  const float* __restrict__ bih,
                                                  const float* __restrict__ Whh,
                                                  const float* __restrict__ bhh,
                                                  const float* __restrict__ bconv,
                                                  int it) {
    __shared__ float Msm[16][64];
    __shared__ float Hsm[16][64];
    __shared__ float GI[16][192];
    __shared__ float GH[16][192];
    int n0 = blockIdx.x * 16;
    int tid = threadIdx.x;
    const float* agg = &g_agg[(size_t)it * N_ * D_];

    for (int idx = tid; idx < 16 * 64; idx += 192) {
        int m = idx >> 6, k = idx & 63;
        int n = n0 + m;
        if (n < N_) {
            float cdeg = fmaxf(g_cnt[n], 1.0f);
            Msm[m][k] = fmaxf(agg[n * 64 + k] / cdeg + bconv[k], 0.f);
            Hsm[m][k] = g_h[n * 64 + k];
        } else {
            Msm[m][k] = 0.f;
            Hsm[m][k] = 0.f;
        }
    }
    __syncthreads();

    float wih[64], whh[64];
    const float* wi = Wih + tid * 64;
    const float* wh = Whh + tid * 64;
#pragma unroll
    for (int k = 0; k < 64; k++) { wih[k] = __ldg(&wi[k]); whh[k] = __ldg(&wh[k]); }
    float bi = bih[tid], bh = bhh[tid];

#pragma unroll 4
    for (int m = 0; m < 16; m++) {
        float ai = bi, ah = bh;
#pragma unroll
        for (int k = 0; k < 64; k++) {
            ai += Msm[m][k] * wih[k];
            ah += Hsm[m][k] * whh[k];
        }
        GI[m][tid] = ai;
        GH[m][tid] = ah;
    }
    __syncthreads();

    for (int idx = tid; idx < 16 * 64; idx += 192) {
        int m = idx >> 6, f = idx & 63;
        int n = n0 + m;
        if (n >= N_) continue;
        float r = sigm(GI[m][f] + GH[m][f]);
        float z = sigm(GI[m][64 + f] + GH[m][64 + f]);
        float nn = tanhf(GI[m][128 + f] + r * GH[m][128 + f]);
        float hnew = (1.f - z) * nn + z * Hsm[m][f];
        g_h[n * 64 + f] = hnew;
    }
}

// ---------------- Set2Set LSTM cell (8 graphs per 256-thread block) ----------------
__global__ void lstm_kernel(const float* __restrict__ Wih, const float* __restrict__ bih,
                            const float* __restrict__ Whh, const float* __restrict__ bhh) {
    __shared__ float qs[8][128];
    __shared__ float hs[8][64];
    __shared__ float gsm[8][256];
    int b0 = blockIdx.x * 8;
    int tid = threadIdx.x;

    for (int idx = tid; idx < 8 * 128; idx += 256) {
        int g = idx >> 7, k = idx & 127;
        int b = b0 + g;
        qs[g][k] = (b < B_) ? g_qstar[b * 128 + k] : 0.f;
    }
    for (int idx = tid; idx < 8 * 64; idx += 256) {
        int g = idx >> 6, k = idx & 63;
        int b = b0 + g;
        hs[g][k] = (b < B_) ? g_hl[b * 64 + k] : 0.f;
    }
    __syncthreads();

    int j = tid;
    float acc[8];
    float bsum = bih[j] + bhh[j];
#pragma unroll
    for (int g = 0; g < 8; g++) acc[g] = bsum;
    const float* wi = Wih + j * 128;
    const float* wh = Whh + j * 64;
#pragma unroll 4
    for (int k = 0; k < 128; k++) {
        float w = __ldg(&wi[k]);
#pragma unroll
        for (int g = 0; g < 8; g++) acc[g] += qs[g][k] * w;
    }
#pragma unroll 4
    for (int k = 0; k < 64; k++) {
        float w = __ldg(&wh[k]);
#pragma unroll
        for (int g = 0; g < 8; g++) acc[g] += hs[g][k] * w;
    }
#pragma unroll
    for (int g = 0; g < 8; g++) gsm[g][j] = acc[g];
    __syncthreads();

    for (int idx = tid; idx < 8 * 64; idx += 256) {
        int g = idx >> 6, f = idx & 63;
        int b = b0 + g;
        if (b >= B_) continue;
        float ig = sigm(gsm[g][f]);
        float fg = sigm(gsm[g][64 + f]);
        float gg = tanhf(gsm[g][128 + f]);
        float og = sigm(gsm[g][192 + f]);
        float c = fg * g_cl[b * 64 + f] + ig * gg;
        float h = og * tanhf(c);
        g_cl[b * 64 + f] = c;
        g_hl[b * 64 + f] = h;
    }
}

// ---------------- attention (segment softmax + weighted sum) per graph ----------------
__global__ void attn_kernel() {
    int b = blockIdx.x;
    int tid = threadIdx.x;   // 128 threads
    __shared__ float qv[64];
    __shared__ float red[128];
    if (tid < 64) qv[tid] = g_hl[b * 64 + tid];
    __syncthreads();

    int s = g_ptr[b], eend = g_ptr[b + 1];

    float lmax = -INFINITY;
    for (int n = s + tid; n < eend; n += 128) {
        const float4* hr = (const float4*)&g_h[n * 64];
        const float4* qq = (const float4*)qv;
        float d = 0.f;
#pragma unroll
        for (int k = 0; k < 16; k++) {
            float4 a = hr[k], c = qq[k];
            d += a.x * c.x + a.y * c.y + a.z * c.z + a.w * c.w;
        }
        g_e[n] = d;
        lmax = fmaxf(lmax, d);
    }
    red[tid] = lmax;
    __syncthreads();
    for (int o = 64; o > 0; o >>= 1) {
        if (tid < o) red[tid] = fmaxf(red[tid], red[tid + o]);
        __syncthreads();
    }
    float mmax = red[0];
    __syncthreads();

    float lsum = 0.f;
    for (int n = s + tid; n < eend; n += 128) {
        float a = expf(g_e[n] - mmax);
        g_e[n] = a;
        lsum += a;
    }
    red[tid] = lsum;
    __syncthreads();
    for (int o = 64; o > 0; o >>= 1) {
        if (tid < o) red[tid] += red[tid + o];
        __syncthreads();
    }
    float den = red[0];
    __syncthreads();

    if (tid < 64) {
        float accr = 0.f;
        for (int n = s; n < eend; n++) accr += g_e[n] * g_h[n * 64 + tid];
        float rv = (den > 0.f) ? accr / den : 0.f;
        g_qstar[b * 128 + tid] = qv[tid];
        g_qstar[b * 128 + 64 + tid] = rv;
    }
}

// ---------------- output head ----------------
__global__ void out_head_kernel(const float* __restrict__ Wo1, const float* __restrict__ bo1,
                                const float* __restrict__ Wo2, const float* __restrict__ bo2,
                                float* __restrict__ out) {
    int b = blockIdx.x;
    int j = threadIdx.x;   // 64
    __shared__ float qs[128];
    __shared__ float hr[64];
    qs[j] = g_qstar[b * 128 + j];
    qs[64 + j] = g_qstar[b * 128 + 64 + j];
    __syncthreads();
    float acc = bo1[j];
    const float* wr = Wo1 + j * 128;
#pragma unroll 4
    for (int k = 0; k < 128; k++) acc += qs[k] * wr[k];
    acc = fmaxf(acc, 0.f) * Wo2[j];
    hr[j] = acc;
    __syncthreads();
    for (int o = 32; o > 0; o >>= 1) {
        if (j < o) hr[j] += hr[j + o];
        __syncthreads();
    }
    if (j == 0) out[b] = hr[0] + bo2[0];
}

// ---------------- host launch ----------------
extern "C" void kernel_launch(void* const* d_in, const int* in_sizes, int n_in,
                              void* d_out, int out_size) {
    const float* x      = (const float*)d_in[0];
    const float* eattr  = (const float*)d_in[1];
    const float* W_in   = (const float*)d_in[2];
    const float* b_in   = (const float*)d_in[3];
    const float* W_e1   = (const float*)d_in[4];
    const float* b_e1   = (const float*)d_in[5];
    const float* W_e2   = (const float*)d_in[6];
    const float* b_e2   = (const float*)d_in[7];
    const float* b_conv = (const float*)d_in[8];
    const float* W_ih   = (const float*)d_in[9];
    const float* b_ih   = (const float*)d_in[10];
    const float* W_hh   = (const float*)d_in[11];
    const float* b_hh   = (const float*)d_in[12];
    const float* W_ih_l = (const float*)d_in[13];
    const float* b_ih_l = (const float*)d_in[14];
    const float* W_hh_l = (const float*)d_in[15];
    const float* b_hh_l = (const float*)d_in[16];
    const float* W_o1   = (const float*)d_in[17];
    const float* b_o1   = (const float*)d_in[18];
    const float* W_o2   = (const float*)d_in[19];
    const float* b_o2   = (const float*)d_in[20];
    const void*  eidx   = d_in[21];
    const void*  batch  = d_in[22];
    float* out = (float*)d_out;

    static bool attr_set = false;
    if (!attr_set) {
        cudaFuncSetAttribute(ew_mma_kernel,
                             cudaFuncAttributeMaxDynamicSharedMemorySize, SM_TOTAL);
        attr_set = true;
    }

    // launches 1-5 (order chosen so ew_mma is launch #6 for ncu -s 5 -c 1)
    detect_kernel<<<1, 32>>>(eidx, batch);                                   // 1
    convert_kernel<<<(E_ + 255) / 256, 256>>>(eidx, batch);                  // 2
    init_zero_kernel<<<(3 * N_ * D_ + 255) / 256, 256>>>();                  // 3
    w2split_kernel<<<(DD_ * D_ + 255) / 256, 256>>>(W_e2);                   // 4
    encoders_kernel<<<((N_ + E_) * D_ + 255) / 256, 256>>>(x, W_in, b_in,
                                                           eattr, W_e1, b_e1); // 5

    // edge-conditioned weight tensor via mma.sync (launch #6 — profiled)
    dim3 ggrid(DD_ / 128, (E_ + 127) / 128);
    ew_mma_kernel<<<ggrid, 256, SM_TOTAL>>>(b_e2);                           // 6

    counts_kernel<<<(E_ + 255) / 256, 256>>>();                              // 7
    scan_ptr_kernel<<<1, 32>>>();                                            // 8

    // 3 message-passing + GRU iterations (agg buffers pre-zeroed)
    for (int it = 0; it < 3; it++) {
        msg_kernel<<<(E_ + 3) / 4, 256>>>(it);
        gru_kernel<<<(N_ + 15) / 16, 192>>>(W_ih, b_ih, W_hh, b_hh, b_conv, it);
    }

    // Set2Set (q_star/hl/cl pre-zeroed)
    for (int it = 0; it < 3; it++) {
        lstm_kernel<<<(B_ + 7) / 8, 256>>>(W_ih_l, b_ih_l, W_hh_l, b_hh_l);
        attn_kernel<<<B_, 128>>>();
    }

    out_head_kernel<<<B_, 64>>>(W_o1, b_o1, W_o2, b_o2, out);
}

// round 8
// speedup vs baseline: 1.2065x; 1.0973x over previous
#include <cuda_runtime.h>
#include <cuda_fp16.h>
#include <math.h>
#include <stdint.h>

#define N_  10000
#define E_  20000
#define B_  400
#define ND_ 32
#define ED_ 16
#define D_  64
#define DD_ 4096   // D*D

// ---------------- scratch (device globals; no cudaMalloc allowed) ----------------
__device__ float g_h[N_ * D_];            // node hidden / out
__device__ __half g_rh[E_ * D_];          // edge MLP hidden, fp16
__device__ __half g_w2h[DD_ * D_];        // W_e2 fp16 [4096][64]
__device__ float g_ew[(size_t)E_ * DD_];  // edge-conditioned weights [E,64,64] (327MB)
__device__ float g_agg[3 * N_ * D_];      // scatter accumulators (one per iteration)
__device__ float g_cnt[N_];               // dst degree
__device__ int   g_src[E_], g_dst[E_], g_batch[N_];
__device__ int   g_flags[2];              // [0]=edge_index is int64, [1]=batch is int64
__device__ int   g_gcnt[B_];
__device__ int   g_ptr[B_ + 1];
__device__ float g_qstar[B_ * 2 * D_];
__device__ float g_hl[B_ * D_];
__device__ float g_cl[B_ * D_];
__device__ float g_e[N_];                 // per-node attention logits / weights

__device__ __forceinline__ float sigm(float x) { return 1.f / (1.f + expf(-x)); }

__device__ __forceinline__ uint32_t smem_u32(const void* p) {
    uint32_t a;
    asm("{ .reg .u64 t; cvta.to.shared.u64 t, %1; cvt.u32.u64 %0, t; }" : "=r"(a) : "l"(p));
    return a;
}
__device__ __forceinline__ void cp16(uint32_t dst, const void* src) {
    asm volatile("cp.async.cg.shared.global [%0], [%1], 16;" :: "r"(dst), "l"(src));
}

// ---------------- W_e2 convert to fp16 (launch #1) ----------------
__global__ void w2split_kernel(const float* __restrict__ W) {
    int i = blockIdx.x * blockDim.x + threadIdx.x;
    if (i >= DD_ * D_) return;
    g_w2h[i] = __float2half(W[i]);
}

// ---------------- fused encoders: in_linear + edge_hidden(+fp16) (launch #2) ----------------
__global__ void encoders_kernel(const float* __restrict__ x,
                                const float* __restrict__ W_in, const float* __restrict__ b_in,
                                const float* __restrict__ ea,
                                const float* __restrict__ W_e1, const float* __restrict__ b_e1) {
    int i = blockIdx.x * blockDim.x + threadIdx.x;
    if (i < N_ * D_) {
        int n = i >> 6, f = i & 63;
        float acc = b_in[f];
        const float* xr = x + n * ND_;
        const float* wr = W_in + f * ND_;
#pragma unroll
        for (int k = 0; k < ND_; k++) acc += xr[k] * wr[k];
        g_h[i] = fmaxf(acc, 0.f);
    } else if (i < N_ * D_ + E_ * D_) {
        int j = i - N_ * D_;
        int e = j >> 6, f = j & 63;
        float acc = b_e1[f];
        const float* er = ea + e * ED_;
        const float* wr = W_e1 + f * ED_;
#pragma unroll
        for (int k = 0; k < ED_; k++) acc += er[k] * wr[k];
        g_rh[j] = __float2half(fmaxf(acc, 0.f));
    }
}

// ---------------- dtype detection (launch #3) ----------------
__global__ void detect_kernel(const void* ei, const void* ba) {
    if (threadIdx.x != 0) return;
    {
        const long long* p = (const long long*)ei;
        int ok = 1;
        for (int i = 0; i < 8; i++) { long long v = p[i]; if (v < 0 || v >= N_) ok = 0; }
        for (int i = 0; i < 8; i++) { long long v = p[2 * E_ / 2 - 8 + i]; if (v < 0 || v >= N_) ok = 0; }
        g_flags[0] = ok;
    }
    {
        const long long* p = (const long long*)ba;
        int ok = 1;
        for (int i = 0; i < 8; i++) { long long v = p[i]; if (v < 0 || v >= B_) ok = 0; }
        for (int i = 0; i < 8; i++) { long long v = p[N_ / 2 - 8 + i]; if (v < 0 || v >= B_) ok = 0; }
        g_flags[1] = ok;
    }
}

// ============ ew GEMM via mma.sync fp16 (single product): g_ew = R @ W_e2^T + b_e2 ====
// CTA tile 128(M edges) x 128(N cols), K=64. 8 warps, warp tile 32x64. (launch #4 - profiled)
#define EWPAD 72     // fp16 row stride (144B): conflict-free ldmatrix phases
#define SM_A 0
#define SM_B (128 * EWPAD * 2)              // 18432
#define SM_TOTAL (SM_B + 128 * EWPAD * 2)   // 36864

__device__ __forceinline__ void ldsm4(uint32_t addr, uint32_t* r) {
    asm volatile("ldmatrix.sync.aligned.m8n8.x4.shared.b16 {%0,%1,%2,%3}, [%4];"
                 : "=r"(r[0]), "=r"(r[1]), "=r"(r[2]), "=r"(r[3]) : "r"(addr));
}
__device__ __forceinline__ void mma_fp16(float* c, const uint32_t* a, uint32_t b0, uint32_t b1) {
    asm volatile(
        "mma.sync.aligned.m16n8k16.row.col.f32.f16.f16.f32 "
        "{%0,%1,%2,%3}, {%4,%5,%6,%7}, {%8,%9}, {%0,%1,%2,%3};"
        : "+f"(c[0]), "+f"(c[1]), "+f"(c[2]), "+f"(c[3])
        : "r"(a[0]), "r"(a[1]), "r"(a[2]), "r"(a[3]), "r"(b0), "r"(b1));
}

__global__ void __launch_bounds__(256) ew_mma_kernel(const float* __restrict__ bias) {
    extern __shared__ char smem[];
    uint32_t sb = smem_u32(smem);
    int tid = threadIdx.x;
    int e0 = blockIdx.y * 128;
    int c0 = blockIdx.x * 128;

    // stage A (128 edges x 64 k) via cp.async; zero-fill tail edges
    for (int i = tid; i < 128 * 8; i += 256) {
        int row = i >> 3, k8 = i & 7;
        int e = e0 + row;
        uint32_t off = (uint32_t)(row * EWPAD + k8 * 8) * 2;
        if (e < E_) cp16(sb + SM_A + off, &g_rh[e * 64 + k8 * 8]);
        else        *(uint4*)(smem + SM_A + off) = make_uint4(0, 0, 0, 0);
    }
    // stage B (128 cols x 64 k)
    for (int i = tid; i < 128 * 8; i += 256) {
        int row = i >> 3, k8 = i & 7;
        uint32_t off = (uint32_t)(row * EWPAD + k8 * 8) * 2;
        cp16(sb + SM_B + off, &g_w2h[(size_t)(c0 + row) * 64 + k8 * 8]);
    }
    asm volatile("cp.async.commit_group;" ::: "memory");
    asm volatile("cp.async.wait_group 0;" ::: "memory");
    __syncthreads();

    int w = tid >> 5, lane = tid & 31;
    int wm = w & 3, wn = w >> 2;      // warp tile: rows wm*32, cols wn*64
    int r8 = lane & 7, q = lane >> 3;

    int a_row = ((q & 1) ? 8 : 0) + r8;
    int a_col = (q >= 2) ? 8 : 0;
    int b_row = ((q >= 2) ? 8 : 0) + r8;
    int b_col = (q & 1) ? 8 : 0;

    float c[2][8][4];
#pragma unroll
    for (int t = 0; t < 2; t++)
#pragma unroll
        for (int n = 0; n < 8; n++)
#pragma unroll
            for (int j = 0; j < 4; j++) c[t][n][j] = 0.f;

#pragma unroll
    for (int k0 = 0; k0 < 64; k0 += 16) {
        uint32_t a[2][4], b[4][4];
#pragma unroll
        for (int t = 0; t < 2; t++) {
            uint32_t ad = sb + SM_A +
                (uint32_t)((wm * 32 + t * 16 + a_row) * EWPAD + k0 + a_col) * 2;
            ldsm4(ad, a[t]);
        }
#pragma unroll
        for (int p = 0; p < 4; p++) {
            uint32_t bd = sb + SM_B +
                (uint32_t)((wn * 64 + p * 16 + b_row) * EWPAD + k0 + b_col) * 2;
            ldsm4(bd, b[p]);
        }
#pragma unroll
        for (int t = 0; t < 2; t++)
#pragma unroll
            for (int n = 0; n < 8; n++) {
                int p = n >> 1, s = (n & 1) * 2;
                mma_fp16(c[t][n], a[t], b[p][s], b[p][s + 1]);
            }
    }

    // epilogue: add bias, store fp32
    int g = lane >> 2, qq = lane & 3;
#pragma unroll
    for (int t = 0; t < 2; t++) {
        int row0 = e0 + wm * 32 + t * 16 + g;
#pragma unroll
        for (int n = 0; n < 8; n++) {
            int col = c0 + wn * 64 + n * 8 + qq * 2;
            float bb0 = __ldg(&bias[col]), bb1 = __ldg(&bias[col + 1]);
            if (row0 < E_) {
                float2 v = make_float2(c[t][n][0] + bb0, c[t][n][1] + bb1);
                *(float2*)&g_ew[(size_t)row0 * DD_ + col] = v;
            }
            if (row0 + 8 < E_) {
                float2 v = make_float2(c[t][n][2] + bb0, c[t][n][3] + bb1);
                *(float2*)&g_ew[(size_t)(row0 + 8) * DD_ + col] = v;
            }
        }
    }
}

// ---------------- index conversion (launch #5) ----------------
__global__ void convert_kernel(const void* ei, const void* ba) {
    int i = blockIdx.x * blockDim.x + threadIdx.x;
    if (i < E_) {
        if (g_flags[0]) {
            const long long* p = (const long long*)ei;
            g_src[i] = (int)p[i];
            g_dst[i] = (int)p[E_ + i];
        } else {
            const int* p = (const int*)ei;
            g_src[i] = p[i];
            g_dst[i] = p[E_ + i];
        }
    }
    if (i < N_) {
        if (g_flags[1]) {
            const long long* p = (const long long*)ba;
            g_batch[i] = (int)p[i];
        } else {
            const int* p = (const int*)ba;
            g_batch[i] = p[i];
        }
    }
}

// ---------------- fused zero init (launch #6) ----------------
__global__ void init_zero_kernel() {
    int i = blockIdx.x * blockDim.x + threadIdx.x;
    int stride = gridDim.x * blockDim.x;
    for (int j = i; j < 3 * N_ * D_; j += stride) g_agg[j] = 0.f;
    if (i < N_) g_cnt[i] = 0.f;
    if (i < B_) g_gcnt[i] = 0;
    if (i < B_ * 2 * D_) g_qstar[i] = 0.f;
    if (i < B_ * D_) { g_hl[i] = 0.f; g_cl[i] = 0.f; }
}

__global__ void counts_kernel() {
    int i = blockIdx.x * blockDim.x + threadIdx.x;
    if (i < E_) atomicAdd(&g_cnt[g_dst[i]], 1.0f);
    if (i < N_) atomicAdd(&g_gcnt[g_batch[i]], 1);
}

__global__ void scan_ptr_kernel() {
    if (threadIdx.x != 0) return;
    int acc = 0;
    g_ptr[0] = 0;
    for (int b = 0; b < B_; b++) { acc += g_gcnt[b]; g_ptr[b + 1] = acc; }
}

// ---------------- message + scatter: agg[dst] += ew[e]^T h[src] ----------------
__global__ void msg_kernel(int it) {
    int sub = threadIdx.x >> 6;
    int f = threadIdx.x & 63;
    int e = blockIdx.x * 4 + sub;
    __shared__ float s[4][64];
    int valid = (e < E_);
    int srcn = 0, dstn = 0;
    if (valid) {
        srcn = g_src[e];
        dstn = g_dst[e];
        s[sub][f] = g_h[srcn * 64 + f];
    }
    __syncthreads();
    if (!valid) return;
    const float* w = &g_ew[(size_t)e * DD_ + f];
    const float* sv = s[sub];
    float acc = 0.f;
#pragma unroll
    for (int d = 0; d < 64; d++) acc += sv[d] * w[d * 64];
    atomicAdd(&g_agg[(size_t)it * N_ * D_ + dstn * 64 + f], acc);
}

// ---------------- GRU update over node tiles of 16 ----------------
__global__ void __launch_bounds__(192) gru_kernel(const float* __restrict__ Wih,
                                                  const float* __restrict__ bih,
                                                  const float* __restrict__ Whh,
                                                  const float* __restrict__ bhh,
                                                  const float* __restrict__ bconv,
                                                  int it) {
    __shared__ float Msm[16][64];
    __shared__ float Hsm[16][64];
    __shared__ float GI[16][192];
    __shared__ float GH[16][192];
    int n0 = blockIdx.x * 16;
    int tid = threadIdx.x;
    const float* agg = &g_agg[(size_t)it * N_ * D_];

    for (int idx = tid; idx < 16 * 64; idx += 192) {
        int m = idx >> 6, k = idx & 63;
        int n = n0 + m;
        if (n < N_) {
            float cdeg = fmaxf(g_cnt[n], 1.0f);
            Msm[m][k] = fmaxf(agg[n * 64 + k] / cdeg + bconv[k], 0.f);
            Hsm[m][k] = g_h[n * 64 + k];
        } else {
            Msm[m][k] = 0.f;
            Hsm[m][k] = 0.f;
        }
    }
    __syncthreads();

    float wih[64], whh[64];
    const float* wi = Wih + tid * 64;
    const float* wh = Whh + tid * 64;
#pragma unroll
    for (int k = 0; k < 64; k++) { wih[k] = __ldg(&wi[k]); whh[k] = __ldg(&wh[k]); }
    float bi = bih[tid], bh = bhh[tid];

#pragma unroll 4
    for (int m = 0; m < 16; m++) {
        float ai = bi, ah = bh;
#pragma unroll
        for (int k = 0; k < 64; k++) {
            ai += Msm[m][k] * wih[k];
            ah += Hsm[m][k] * whh[k];
        }
        GI[m][tid] = ai;
        GH[m][tid] = ah;
    }
    __syncthreads();

    for (int idx = tid; idx < 16 * 64; idx += 192) {
        int m = idx >> 6, f = idx & 63;
        int n = n0 + m;
        if (n >= N_) continue;
        float r = sigm(GI[m][f] + GH[m][f]);
        float z = sigm(GI[m][64 + f] + GH[m][64 + f]);
        float nn = tanhf(GI[m][128 + f] + r * GH[m][128 + f]);
        float hnew = (1.f - z) * nn + z * Hsm[m][f];
        g_h[n * 64 + f] = hnew;
    }
}

// ---------------- Set2Set LSTM cell (8 graphs per 256-thread block) ----------------
__global__ void lstm_kernel(const float* __restrict__ Wih, const float* __restrict__ bih,
                            const float* __restrict__ Whh, const float* __restrict__ bhh) {
    __shared__ float qs[8][128];
    __shared__ float hs[8][64];
    __shared__ float gsm[8][256];
    int b0 = blockIdx.x * 8;
    int tid = threadIdx.x;

    for (int idx = tid; idx < 8 * 128; idx += 256) {
        int g = idx >> 7, k = idx & 127;
        int b = b0 + g;
        qs[g][k] = (b < B_) ? g_qstar[b * 128 + k] : 0.f;
    }
    for (int idx = tid; idx < 8 * 64; idx += 256) {
        int g = idx >> 6, k = idx & 63;
        int b = b0 + g;
        hs[g][k] = (b < B_) ? g_hl[b * 64 + k] : 0.f;
    }
    __syncthreads();

    int j = tid;
    float acc[8];
    float bsum = bih[j] + bhh[j];
#pragma unroll
    for (int g = 0; g < 8; g++) acc[g] = bsum;
    const float* wi = Wih + j * 128;
    const float* wh = Whh + j * 64;
#pragma unroll 4
    for (int k = 0; k < 128; k++) {
        float w = __ldg(&wi[k]);
#pragma unroll
        for (int g = 0; g < 8; g++) acc[g] += qs[g][k] * w;
    }
#pragma unroll 4
    for (int k = 0; k < 64; k++) {
        float w = __ldg(&wh[k]);
#pragma unroll
        for (int g = 0; g < 8; g++) acc[g] += hs[g][k] * w;
    }
#pragma unroll
    for (int g = 0; g < 8; g++) gsm[g][j] = acc[g];
    __syncthreads();

    for (int idx = tid; idx < 8 * 64; idx += 256) {
        int g = idx >> 6, f = idx & 63;
        int b = b0 + g;
        if (b >= B_) continue;
        float ig = sigm(gsm[g][f]);
        float fg = sigm(gsm[g][64 + f]);
        float gg = tanhf(gsm[g][128 + f]);
        float og = sigm(gsm[g][192 + f]);
        float c = fg * g_cl[b * 64 + f] + ig * gg;
        float h = og * tanhf(c);
        g_cl[b * 64 + f] = c;
        g_hl[b * 64 + f] = h;
    }
}

// ---------------- attention (segment softmax + weighted sum) per graph ----------------
__global__ void attn_kernel() {
    int b = blockIdx.x;
    int tid = threadIdx.x;   // 128 threads
    __shared__ float qv[64];
    __shared__ float red[128];
    if (tid < 64) qv[tid] = g_hl[b * 64 + tid];
    __syncthreads();

    int s = g_ptr[b], eend = g_ptr[b + 1];

    float lmax = -INFINITY;
    for (int n = s + tid; n < eend; n += 128) {
        const float4* hr = (const float4*)&g_h[n * 64];
        const float4* qq = (const float4*)qv;
        float d = 0.f;
#pragma unroll
        for (int k = 0; k < 16; k++) {
            float4 a = hr[k], c = qq[k];
            d += a.x * c.x + a.y * c.y + a.z * c.z + a.w * c.w;
        }
        g_e[n] = d;
        lmax = fmaxf(lmax, d);
    }
    red[tid] = lmax;
    __syncthreads();
    for (int o = 64; o > 0; o >>= 1) {
        if (tid < o) red[tid] = fmaxf(red[tid], red[tid + o]);
        __syncthreads();
    }
    float mmax = red[0];
    __syncthreads();

    float lsum = 0.f;
    for (int n = s + tid; n < eend; n += 128) {
        float a = expf(g_e[n] - mmax);
        g_e[n] = a;
        lsum += a;
    }
    red[tid] = lsum;
    __syncthreads();
    for (int o = 64; o > 0; o >>= 1) {
        if (tid < o) red[tid] += red[tid + o];
        __syncthreads();
    }
    float den = red[0];
    __syncthreads();

    if (tid < 64) {
        float accr = 0.f;
        for (int n = s; n < eend; n++) accr += g_e[n] * g_h[n * 64 + tid];
        float rv = (den > 0.f) ? accr / den : 0.f;
        g_qstar[b * 128 + tid] = qv[tid];
        g_qstar[b * 128 + 64 + tid] = rv;
    }
}

// ---------------- output head ----------------
__global__ void out_head_kernel(const float* __restrict__ Wo1, const float* __restrict__ bo1,
                                const float* __restrict__ Wo2, const float* __restrict__ bo2,
                                float* __restrict__ out) {
    int b = blockIdx.x;
    int j = threadIdx.x;   // 64
    __shared__ float qs[128];
    __shared__ float hr[64];
    qs[j] = g_qstar[b * 128 + j];
    qs[64 + j] = g_qstar[b * 128 + 64 + j];
    __syncthreads();
    float acc = bo1[j];
    const float* wr = Wo1 + j * 128;
#pragma unroll 4
    for (int k = 0; k < 128; k++) acc += qs[k] * wr[k];
    acc = fmaxf(acc, 0.f) * Wo2[j];
    hr[j] = acc;
    __syncthreads();
    for (int o = 32; o > 0; o >>= 1) {
        if (j < o) hr[j] += hr[j + o];
        __syncthreads();
    }
    if (j == 0) out[b] = hr[0] + bo2[0];
}

// ---------------- host launch ----------------
extern "C" void kernel_launch(void* const* d_in, const int* in_sizes, int n_in,
                              void* d_out, int out_size) {
    const float* x      = (const float*)d_in[0];
    const float* eattr  = (const float*)d_in[1];
    const float* W_in   = (const float*)d_in[2];
    const float* b_in   = (const float*)d_in[3];
    const float* W_e1   = (const float*)d_in[4];
    const float* b_e1   = (const float*)d_in[5];
    const float* W_e2   = (const float*)d_in[6];
    const float* b_e2   = (const float*)d_in[7];
    const float* b_conv = (const float*)d_in[8];
    const float* W_ih   = (const float*)d_in[9];
    const float* b_ih   = (const float*)d_in[10];
    const float* W_hh   = (const float*)d_in[11];
    const float* b_hh   = (const float*)d_in[12];
    const float* W_ih_l = (const float*)d_in[13];
    const float* b_ih_l = (const float*)d_in[14];
    const float* W_hh_l = (const float*)d_in[15];
    const float* b_hh_l = (const float*)d_in[16];
    const float* W_o1   = (const float*)d_in[17];
    const float* b_o1   = (const float*)d_in[18];
    const float* W_o2   = (const float*)d_in[19];
    const float* b_o2   = (const float*)d_in[20];
    const void*  eidx   = d_in[21];
    const void*  batch  = d_in[22];
    float* out = (float*)d_out;

    static bool attr_set = false;
    if (!attr_set) {
        cudaFuncSetAttribute(ew_mma_kernel,
                             cudaFuncAttributeMaxDynamicSharedMemorySize, SM_TOTAL);
        attr_set = true;
    }

    // order chosen so ew_mma is the 4th launch (what ncu actually captures)
    w2split_kernel<<<(DD_ * D_ + 255) / 256, 256>>>(W_e2);                   // 1
    encoders_kernel<<<((N_ + E_) * D_ + 255) / 256, 256>>>(x, W_in, b_in,
                                                           eattr, W_e1, b_e1); // 2
    detect_kernel<<<1, 32>>>(eidx, batch);                                   // 3

    dim3 ggrid(DD_ / 128, (E_ + 127) / 128);
    ew_mma_kernel<<<ggrid, 256, SM_TOTAL>>>(b_e2);                           // 4 (profiled)

    convert_kernel<<<(E_ + 255) / 256, 256>>>(eidx, batch);                  // 5
    init_zero_kernel<<<(3 * N_ * D_ + 255) / 256, 256>>>();                  // 6
    counts_kernel<<<(E_ + 255) / 256, 256>>>();                              // 7
    scan_ptr_kernel<<<1, 32>>>();                                            // 8

    // 3 message-passing + GRU iterations (agg buffers pre-zeroed)
    for (int it = 0; it < 3; it++) {
        msg_kernel<<<(E_ + 3) / 4, 256>>>(it);
        gru_kernel<<<(N_ + 15) / 16, 192>>>(W_ih, b_ih, W_hh, b_hh, b_conv, it);
    }

    // Set2Set (q_star/hl/cl pre-zeroed)
    for (int it = 0; it < 3; it++) {
        lstm_kernel<<<(B_ + 7) / 8, 256>>>(W_ih_l, b_ih_l, W_hh_l, b_hh_l);
        attn_kernel<<<B_, 128>>>();
    }

    out_head_kernel<<<B_, 64>>>(W_o1, b_o1, W_o2, b_o2, out);
}

// round 9
// speedup vs baseline: 1.3333x; 1.1051x over previous
#include <cuda_runtime.h>
#include <cuda_fp16.h>
#include <math.h>
#include <stdint.h>

#define N_  10000
#define E_  20000
#define B_  400
#define ND_ 32
#define ED_ 16
#define D_  64
#define DD_ 4096   // D*D

// ---------------- scratch (device globals; no cudaMalloc allowed) ----------------
__device__ float g_h[N_ * D_];            // node hidden / out
__device__ __half g_rh[E_ * D_];          // edge MLP hidden, fp16
__device__ __half g_w2h[DD_ * D_];        // W_e2 fp16 [4096][64]
__device__ __half g_ew16[(size_t)E_ * DD_]; // edge-conditioned weights fp16 (164MB)
__device__ float g_agg[3 * N_ * D_];      // scatter accumulators (one per iteration)
__device__ float g_cnt[N_];               // dst degree
__device__ int   g_src[E_], g_dst[E_], g_batch[N_];
__device__ int   g_flags[2];              // [0]=edge_index is int64, [1]=batch is int64
__device__ int   g_gcnt[B_];
__device__ int   g_ptr[B_ + 1];
__device__ float g_qstar[B_ * 2 * D_];
__device__ float g_hl[B_ * D_];
__device__ float g_cl[B_ * D_];
__device__ float g_e[N_];                 // per-node attention logits / weights

__device__ __forceinline__ float sigm(float x) { return 1.f / (1.f + expf(-x)); }

__device__ __forceinline__ uint32_t smem_u32(const void* p) {
    uint32_t a;
    asm("{ .reg .u64 t; cvta.to.shared.u64 t, %1; cvt.u32.u64 %0, t; }" : "=r"(a) : "l"(p));
    return a;
}
__device__ __forceinline__ void cp16(uint32_t dst, const void* src) {
    asm volatile("cp.async.cg.shared.global [%0], [%1], 16;" :: "r"(dst), "l"(src));
}

// ---------------- W_e2 convert to fp16 (launch #1) ----------------
__global__ void w2split_kernel(const float* __restrict__ W) {
    int i = blockIdx.x * blockDim.x + threadIdx.x;
    if (i >= DD_ * D_) return;
    g_w2h[i] = __float2half(W[i]);
}

// ---------------- fused encoders: in_linear + edge_hidden(+fp16) (launch #2) ----------------
__global__ void encoders_kernel(const float* __restrict__ x,
                                const float* __restrict__ W_in, const float* __restrict__ b_in,
                                const float* __restrict__ ea,
                                const float* __restrict__ W_e1, const float* __restrict__ b_e1) {
    int i = blockIdx.x * blockDim.x + threadIdx.x;
    if (i < N_ * D_) {
        int n = i >> 6, f = i & 63;
        float acc = b_in[f];
        const float* xr = x + n * ND_;
        const float* wr = W_in + f * ND_;
#pragma unroll
        for (int k = 0; k < ND_; k++) acc += xr[k] * wr[k];
        g_h[i] = fmaxf(acc, 0.f);
    } else if (i < N_ * D_ + E_ * D_) {
        int j = i - N_ * D_;
        int e = j >> 6, f = j & 63;
        float acc = b_e1[f];
        const float* er = ea + e * ED_;
        const float* wr = W_e1 + f * ED_;
#pragma unroll
        for (int k = 0; k < ED_; k++) acc += er[k] * wr[k];
        g_rh[j] = __float2half(fmaxf(acc, 0.f));
    }
}

// ---------------- dtype detection (launch #3) ----------------
__global__ void detect_kernel(const void* ei, const void* ba) {
    if (threadIdx.x != 0) return;
    {
        const long long* p = (const long long*)ei;
        int ok = 1;
        for (int i = 0; i < 8; i++) { long long v = p[i]; if (v < 0 || v >= N_) ok = 0; }
        for (int i = 0; i < 8; i++) { long long v = p[2 * E_ / 2 - 8 + i]; if (v < 0 || v >= N_) ok = 0; }
        g_flags[0] = ok;
    }
    {
        const long long* p = (const long long*)ba;
        int ok = 1;
        for (int i = 0; i < 8; i++) { long long v = p[i]; if (v < 0 || v >= B_) ok = 0; }
        for (int i = 0; i < 8; i++) { long long v = p[N_ / 2 - 8 + i]; if (v < 0 || v >= B_) ok = 0; }
        g_flags[1] = ok;
    }
}

// ============ ew GEMM via mma.sync fp16: g_ew16 = R @ W_e2^T + b_e2 (fp16 out) ====
// CTA tile 128(M edges) x 128(N cols), K=64. 8 warps, warp tile 32x64. (launch #4 - profiled)
#define EWPAD 72     // fp16 row stride (144B): conflict-free ldmatrix phases
#define SM_A 0
#define SM_B (128 * EWPAD * 2)              // 18432
#define SM_TOTAL (SM_B + 128 * EWPAD * 2)   // 36864

__device__ __forceinline__ void ldsm4(uint32_t addr, uint32_t* r) {
    asm volatile("ldmatrix.sync.aligned.m8n8.x4.shared.b16 {%0,%1,%2,%3}, [%4];"
                 : "=r"(r[0]), "=r"(r[1]), "=r"(r[2]), "=r"(r[3]) : "r"(addr));
}
__device__ __forceinline__ void mma_fp16(float* c, const uint32_t* a, uint32_t b0, uint32_t b1) {
    asm volatile(
        "mma.sync.aligned.m16n8k16.row.col.f32.f16.f16.f32 "
        "{%0,%1,%2,%3}, {%4,%5,%6,%7}, {%8,%9}, {%0,%1,%2,%3};"
        : "+f"(c[0]), "+f"(c[1]), "+f"(c[2]), "+f"(c[3])
        : "r"(a[0]), "r"(a[1]), "r"(a[2]), "r"(a[3]), "r"(b0), "r"(b1));
}

__global__ void __launch_bounds__(256) ew_mma_kernel(const float* __restrict__ bias) {
    extern __shared__ char smem[];
    uint32_t sb = smem_u32(smem);
    int tid = threadIdx.x;
    int e0 = blockIdx.y * 128;
    int c0 = blockIdx.x * 128;

    // stage A (128 edges x 64 k) via cp.async; zero-fill tail edges
    for (int i = tid; i < 128 * 8; i += 256) {
        int row = i >> 3, k8 = i & 7;
        int e = e0 + row;
        uint32_t off = (uint32_t)(row * EWPAD + k8 * 8) * 2;
        if (e < E_) cp16(sb + SM_A + off, &g_rh[e * 64 + k8 * 8]);
        else        *(uint4*)(smem + SM_A + off) = make_uint4(0, 0, 0, 0);
    }
    // stage B (128 cols x 64 k)
    for (int i = tid; i < 128 * 8; i += 256) {
        int row = i >> 3, k8 = i & 7;
        uint32_t off = (uint32_t)(row * EWPAD + k8 * 8) * 2;
        cp16(sb + SM_B + off, &g_w2h[(size_t)(c0 + row) * 64 + k8 * 8]);
    }
    asm volatile("cp.async.commit_group;" ::: "memory");
    asm volatile("cp.async.wait_group 0;" ::: "memory");
    __syncthreads();

    int w = tid >> 5, lane = tid & 31;
    int wm = w & 3, wn = w >> 2;      // warp tile: rows wm*32, cols wn*64
    int r8 = lane & 7, q = lane >> 3;

    int a_row = ((q & 1) ? 8 : 0) + r8;
    int a_col = (q >= 2) ? 8 : 0;
    int b_row = ((q >= 2) ? 8 : 0) + r8;
    int b_col = (q & 1) ? 8 : 0;

    float c[2][8][4];
#pragma unroll
    for (int t = 0; t < 2; t++)
#pragma unroll
        for (int n = 0; n < 8; n++)
#pragma unroll
            for (int j = 0; j < 4; j++) c[t][n][j] = 0.f;

#pragma unroll
    for (int k0 = 0; k0 < 64; k0 += 16) {
        uint32_t a[2][4], b[4][4];
#pragma unroll
        for (int t = 0; t < 2; t++) {
            uint32_t ad = sb + SM_A +
                (uint32_t)((wm * 32 + t * 16 + a_row) * EWPAD + k0 + a_col) * 2;
            ldsm4(ad, a[t]);
        }
#pragma unroll
        for (int p = 0; p < 4; p++) {
            uint32_t bd = sb + SM_B +
                (uint32_t)((wn * 64 + p * 16 + b_row) * EWPAD + k0 + b_col) * 2;
            ldsm4(bd, b[p]);
        }
#pragma unroll
        for (int t = 0; t < 2; t++)
#pragma unroll
            for (int n = 0; n < 8; n++) {
                int p = n >> 1, s = (n & 1) * 2;
                mma_fp16(c[t][n], a[t], b[p][s], b[p][s + 1]);
            }
    }

    // epilogue: add bias, store fp16
    int g = lane >> 2, qq = lane & 3;
#pragma unroll
    for (int t = 0; t < 2; t++) {
        int row0 = e0 + wm * 32 + t * 16 + g;
#pragma unroll
        for (int n = 0; n < 8; n++) {
            int col = c0 + wn * 64 + n * 8 + qq * 2;
            float bb0 = __ldg(&bias[col]), bb1 = __ldg(&bias[col + 1]);
            if (row0 < E_) {
                __half2 v = __floats2half2_rn(c[t][n][0] + bb0, c[t][n][1] + bb1);
                *(__half2*)&g_ew16[(size_t)row0 * DD_ + col] = v;
            }
            if (row0 + 8 < E_) {
                __half2 v = __floats2half2_rn(c[t][n][2] + bb0, c[t][n][3] + bb1);
                *(__half2*)&g_ew16[(size_t)(row0 + 8) * DD_ + col] = v;
            }
        }
    }
}

// ---------------- index conversion (launch #5) ----------------
__global__ void convert_kernel(const void* ei, const void* ba) {
    int i = blockIdx.x * blockDim.x + threadIdx.x;
    if (i < E_) {
        if (g_flags[0]) {
            const long long* p = (const long long*)ei;
            g_src[i] = (int)p[i];
            g_dst[i] = (int)p[E_ + i];
        } else {
            const int* p = (const int*)ei;
            g_src[i] = p[i];
            g_dst[i] = p[E_ + i];
        }
    }
    if (i < N_) {
        if (g_flags[1]) {
            const long long* p = (const long long*)ba;
            g_batch[i] = (int)p[i];
        } else {
            const int* p = (const int*)ba;
            g_batch[i] = p[i];
        }
    }
}

// ---------------- fused zero init (launch #6) ----------------
__global__ void init_zero_kernel() {
    int i = blockIdx.x * blockDim.x + threadIdx.x;
    int stride = gridDim.x * blockDim.x;
    for (int j = i; j < 3 * N_ * D_; j += stride) g_agg[j] = 0.f;
    if (i < N_) g_cnt[i] = 0.f;
    if (i < B_) g_gcnt[i] = 0;
    if (i < B_ * 2 * D_) g_qstar[i] = 0.f;
    if (i < B_ * D_) { g_hl[i] = 0.f; g_cl[i] = 0.f; }
}

__global__ void counts_kernel() {
    int i = blockIdx.x * blockDim.x + threadIdx.x;
    if (i < E_) atomicAdd(&g_cnt[g_dst[i]], 1.0f);
    if (i < N_) atomicAdd(&g_gcnt[g_batch[i]], 1);
}

__global__ void scan_ptr_kernel() {
    if (threadIdx.x != 0) return;
    int acc = 0;
    g_ptr[0] = 0;
    for (int b = 0; b < B_; b++) { acc += g_gcnt[b]; g_ptr[b + 1] = acc; }
}

// ---------------- message + scatter: agg[dst] += ew[e]^T h[src] (fp16 ew) -------
// One warp per edge; lane covers f = {2*lane, 2*lane+1} via half2.
__global__ void __launch_bounds__(128) msg_kernel(int it) {
    int sub = threadIdx.x >> 5;      // 4 edges per 128-thread block
    int lane = threadIdx.x & 31;
    int e = blockIdx.x * 4 + sub;
    __shared__ float s[4][64];
    if (e >= E_) return;
    int srcn = g_src[e];
    int dstn = g_dst[e];
    ((float2*)s[sub])[lane] = ((const float2*)&g_h[srcn * 64])[lane];
    __syncwarp();

    const __half2* wp = (const __half2*)&g_ew16[(size_t)e * DD_] + lane;
    const float* sv = s[sub];
    float2 acc = make_float2(0.f, 0.f);
#pragma unroll
    for (int d = 0; d < 64; d++) {
        float2 wv = __half22float2(wp[d * 32]);
        float hv = sv[d];
        acc.x += hv * wv.x;
        acc.y += hv * wv.y;
    }
    float* agg = &g_agg[(size_t)it * N_ * D_ + dstn * 64 + 2 * lane];
    atomicAdd(agg, acc.x);
    atomicAdd(agg + 1, acc.y);
}

// ---------------- GRU update over node tiles of 16 ----------------
__global__ void __launch_bounds__(192) gru_kernel(const float* __restrict__ Wih,
                                                  const float* __restrict__ bih,
                                                  const float* __restrict__ Whh,
                                                  const float* __restrict__ bhh,
                                                  const float* __restrict__ bconv,
                                                  int it) {
    __shared__ float Msm[16][64];
    __shared__ float Hsm[16][64];
    __shared__ float GI[16][192];
    __shared__ float GH[16][192];
    int n0 = blockIdx.x * 16;
    int tid = threadIdx.x;
    const float* agg = &g_agg[(size_t)it * N_ * D_];

    for (int idx = tid; idx < 16 * 64; idx += 192) {
        int m = idx >> 6, k = idx & 63;
        int n = n0 + m;
        if (n < N_) {
            float cdeg = fmaxf(g_cnt[n], 1.0f);
            Msm[m][k] = fmaxf(agg[n * 64 + k] / cdeg + bconv[k], 0.f);
            Hsm[m][k] = g_h[n * 64 + k];
        } else {
            Msm[m][k] = 0.f;
            Hsm[m][k] = 0.f;
        }
    }
    __syncthreads();

    float wih[64], whh[64];
    const float* wi = Wih + tid * 64;
    const float* wh = Whh + tid * 64;
#pragma unroll
    for (int k = 0; k < 64; k++) { wih[k] = __ldg(&wi[k]); whh[k] = __ldg(&wh[k]); }
    float bi = bih[tid], bh = bhh[tid];

#pragma unroll 4
    for (int m = 0; m < 16; m++) {
        float ai = bi, ah = bh;
#pragma unroll
        for (int k = 0; k < 64; k++) {
            ai += Msm[m][k] * wih[k];
            ah += Hsm[m][k] * whh[k];
        }
        GI[m][tid] = ai;
        GH[m][tid] = ah;
    }
    __syncthreads();

    for (int idx = tid; idx < 16 * 64; idx += 192) {
        int m = idx >> 6, f = idx & 63;
        int n = n0 + m;
        if (n >= N_) continue;
        float r = sigm(GI[m][f] + GH[m][f]);
        float z = sigm(GI[m][64 + f] + GH[m][64 + f]);
        float nn = tanhf(GI[m][128 + f] + r * GH[m][128 + f]);
        float hnew = (1.f - z) * nn + z * Hsm[m][f];
        g_h[n * 64 + f] = hnew;
    }
}

// ---------------- Set2Set LSTM cell (8 graphs per 256-thread block) ----------------
__global__ void lstm_kernel(const float* __restrict__ Wih, const float* __restrict__ bih,
                            const float* __restrict__ Whh, const float* __restrict__ bhh) {
    __shared__ float qs[8][128];
    __shared__ float hs[8][64];
    __shared__ float gsm[8][256];
    int b0 = blockIdx.x * 8;
    int tid = threadIdx.x;

    for (int idx = tid; idx < 8 * 128; idx += 256) {
        int g = idx >> 7, k = idx & 127;
        int b = b0 + g;
        qs[g][k] = (b < B_) ? g_qstar[b * 128 + k] : 0.f;
    }
    for (int idx = tid; idx < 8 * 64; idx += 256) {
        int g = idx >> 6, k = idx & 63;
        int b = b0 + g;
        hs[g][k] = (b < B_) ? g_hl[b * 64 + k] : 0.f;
    }
    __syncthreads();

    int j = tid;
    float acc[8];
    float bsum = bih[j] + bhh[j];
#pragma unroll
    for (int g = 0; g < 8; g++) acc[g] = bsum;
    const float* wi = Wih + j * 128;
    const float* wh = Whh + j * 64;
#pragma unroll 4
    for (int k = 0; k < 128; k++) {
        float w = __ldg(&wi[k]);
#pragma unroll
        for (int g = 0; g < 8; g++) acc[g] += qs[g][k] * w;
    }
#pragma unroll 4
    for (int k = 0; k < 64; k++) {
        float w = __ldg(&wh[k]);
#pragma unroll
        for (int g = 0; g < 8; g++) acc[g] += hs[g][k] * w;
    }
#pragma unroll
    for (int g = 0; g < 8; g++) gsm[g][j] = acc[g];
    __syncthreads();

    for (int idx = tid; idx < 8 * 64; idx += 256) {
        int g = idx >> 6, f = idx & 63;
        int b = b0 + g;
        if (b >= B_) continue;
        float ig = sigm(gsm[g][f]);
        float fg = sigm(gsm[g][64 + f]);
        float gg = tanhf(gsm[g][128 + f]);
        float og = sigm(gsm[g][192 + f]);
        float c = fg * g_cl[b * 64 + f] + ig * gg;
        float h = og * tanhf(c);
        g_cl[b * 64 + f] = c;
        g_hl[b * 64 + f] = h;
    }
}

// ---------------- attention (segment softmax + weighted sum) per graph ----------------
__global__ void attn_kernel() {
    int b = blockIdx.x;
    int tid = threadIdx.x;   // 128 threads
    __shared__ float qv[64];
    __shared__ float red[128];
    if (tid < 64) qv[tid] = g_hl[b * 64 + tid];
    __syncthreads();

    int s = g_ptr[b], eend = g_ptr[b + 1];

    float lmax = -INFINITY;
    for (int n = s + tid; n < eend; n += 128) {
        const float4* hr = (const float4*)&g_h[n * 64];
        const float4* qq = (const float4*)qv;
        float d = 0.f;
#pragma unroll
        for (int k = 0; k < 16; k++) {
            float4 a = hr[k], c = qq[k];
            d += a.x * c.x + a.y * c.y + a.z * c.z + a.w * c.w;
        }
        g_e[n] = d;
        lmax = fmaxf(lmax, d);
    }
    red[tid] = lmax;
    __syncthreads();
    for (int o = 64; o > 0; o >>= 1) {
        if (tid < o) red[tid] = fmaxf(red[tid], red[tid + o]);
        __syncthreads();
    }
    float mmax = red[0];
    __syncthreads();

    float lsum = 0.f;
    for (int n = s + tid; n < eend; n += 128) {
        float a = expf(g_e[n] - mmax);
        g_e[n] = a;
        lsum += a;
    }
    red[tid] = lsum;
    __syncthreads();
    for (int o = 64; o > 0; o >>= 1) {
        if (tid < o) red[tid] += red[tid + o];
        __syncthreads();
    }
    float den = red[0];
    __syncthreads();

    if (tid < 64) {
        float accr = 0.f;
        for (int n = s; n < eend; n++) accr += g_e[n] * g_h[n * 64 + tid];
        float rv = (den > 0.f) ? accr / den : 0.f;
        g_qstar[b * 128 + tid] = qv[tid];
        g_qstar[b * 128 + 64 + tid] = rv;
    }
}

// ---------------- output head ----------------
__global__ void out_head_kernel(const float* __restrict__ Wo1, const float* __restrict__ bo1,
                                const float* __restrict__ Wo2, const float* __restrict__ bo2,
                                float* __restrict__ out) {
    int b = blockIdx.x;
    int j = threadIdx.x;   // 64
    __shared__ float qs[128];
    __shared__ float hr[64];
    qs[j] = g_qstar[b * 128 + j];
    qs[64 + j] = g_qstar[b * 128 + 64 + j];
    __syncthreads();
    float acc = bo1[j];
    const float* wr = Wo1 + j * 128;
#pragma unroll 4
    for (int k = 0; k < 128; k++) acc += qs[k] * wr[k];
    acc = fmaxf(acc, 0.f) * Wo2[j];
    hr[j] = acc;
    __syncthreads();
    for (int o = 32; o > 0; o >>= 1) {
        if (j < o) hr[j] += hr[j + o];
        __syncthreads();
    }
    if (j == 0) out[b] = hr[0] + bo2[0];
}

// ---------------- host launch ----------------
extern "C" void kernel_launch(void* const* d_in, const int* in_sizes, int n_in,
                              void* d_out, int out_size) {
    const float* x      = (const float*)d_in[0];
    const float* eattr  = (const float*)d_in[1];
    const float* W_in   = (const float*)d_in[2];
    const float* b_in   = (const float*)d_in[3];
    const float* W_e1   = (const float*)d_in[4];
    const float* b_e1   = (const float*)d_in[5];
    const float* W_e2   = (const float*)d_in[6];
    const float* b_e2   = (const float*)d_in[7];
    const float* b_conv = (const float*)d_in[8];
    const float* W_ih   = (const float*)d_in[9];
    const float* b_ih   = (const float*)d_in[10];
    const float* W_hh   = (const float*)d_in[11];
    const float* b_hh   = (const float*)d_in[12];
    const float* W_ih_l = (const float*)d_in[13];
    const float* b_ih_l = (const float*)d_in[14];
    const float* W_hh_l = (const float*)d_in[15];
    const float* b_hh_l = (const float*)d_in[16];
    const float* W_o1   = (const float*)d_in[17];
    const float* b_o1   = (const float*)d_in[18];
    const float* W_o2   = (const float*)d_in[19];
    const float* b_o2   = (const float*)d_in[20];
    const void*  eidx   = d_in[21];
    const void*  batch  = d_in[22];
    float* out = (float*)d_out;

    static bool attr_set = false;
    if (!attr_set) {
        cudaFuncSetAttribute(ew_mma_kernel,
                             cudaFuncAttributeMaxDynamicSharedMemorySize, SM_TOTAL);
        attr_set = true;
    }

    // order chosen so ew_mma is the 4th launch (what ncu actually captures)
    w2split_kernel<<<(DD_ * D_ + 255) / 256, 256>>>(W_e2);                   // 1
    encoders_kernel<<<((N_ + E_) * D_ + 255) / 256, 256>>>(x, W_in, b_in,
                                                           eattr, W_e1, b_e1); // 2
    detect_kernel<<<1, 32>>>(eidx, batch);                                   // 3

    dim3 ggrid(DD_ / 128, (E_ + 127) / 128);
    ew_mma_kernel<<<ggrid, 256, SM_TOTAL>>>(b_e2);                           // 4 (profiled)

    convert_kernel<<<(E_ + 255) / 256, 256>>>(eidx, batch);                  // 5
    init_zero_kernel<<<(3 * N_ * D_ + 255) / 256, 256>>>();                  // 6
    counts_kernel<<<(E_ + 255) / 256, 256>>>();                              // 7
    scan_ptr_kernel<<<1, 32>>>();                                            // 8

    // 3 message-passing + GRU iterations (agg buffers pre-zeroed)
    for (int it = 0; it < 3; it++) {
        msg_kernel<<<(E_ + 3) / 4, 128>>>(it);
        gru_kernel<<<(N_ + 15) / 16, 192>>>(W_ih, b_ih, W_hh, b_hh, b_conv, it);
    }

    // Set2Set (q_star/hl/cl pre-zeroed)
    for (int it = 0; it < 3; it++) {
        lstm_kernel<<<(B_ + 7) / 8, 256>>>(W_ih_l, b_ih_l, W_hh_l, b_hh_l);
        attn_kernel<<<B_, 128>>>();
    }

    out_head_kernel<<<B_, 64>>>(W_o1, b_o1, W_o2, b_o2, out);
}